// round 2
// baseline (speedup 1.0000x reference)
#include <cuda_runtime.h>
#include <cstdint>

// ---------------------------------------------------------------------------
// Problem constants
// ---------------------------------------------------------------------------
#define B_SZ   8
#define T_SZ   2048
#define C_SZ   1024
#define H_SZ   16
#define DH     64          // head dim
#define BH     (B_SZ * H_SZ)     // 128
#define C3     (3 * C_SZ)        // 3072
#define M_ROWS (B_SZ * T_SZ)     // 16384
#define MW     64          // fine window m
#define PP     8           // coarse keys per block
#define NLEV   4           // coarse levels

// Pooled K/V: level l0 (0..3) -> stride s = 8<<l0, count nl = 256>>l0 per bh.
__device__ __constant__ size_t POOL_OFF[4] = {
    0,
    (size_t)BH * 256 * DH,
    (size_t)BH * 256 * DH + (size_t)BH * 128 * DH,
    (size_t)BH * 256 * DH + (size_t)BH * 128 * DH + (size_t)BH * 64 * DH
};
#define POOL_TOTAL ((size_t)BH * (256 + 128 + 64 + 32) * DH)  // 3,932,160 floats

// ---------------------------------------------------------------------------
// Scratch (static device allocations; no cudaMalloc anywhere)
// ---------------------------------------------------------------------------
__device__ float g_qkv [(size_t)M_ROWS * C3];     // 201 MB
__device__ float g_attn[(size_t)M_ROWS * C_SZ];   //  64 MB
__device__ float g_kpool[POOL_TOTAL];             //  16 MB
__device__ float g_vpool[POOL_TOTAL];             //  16 MB

// ---------------------------------------------------------------------------
// SGEMM: C[M,N] = A[M,K] @ B[K,N] + bias[N]   (fp32, 128x128x8, 8x8/thread)
// ---------------------------------------------------------------------------
#define GBM 128
#define GBN 128
#define GBK 8
#define GTM 8
#define GTN 8

__global__ __launch_bounds__(256, 2)
void sgemm_bias(const float* __restrict__ A, const float* __restrict__ Bm,
                const float* __restrict__ bias, float* __restrict__ C,
                int M, int N, int K)
{
    __shared__ float sA[GBK][GBM];
    __shared__ float sB[GBK][GBN];

    const int tid  = threadIdx.x;          // 256 threads
    const int brow = blockIdx.y;
    const int bcol = blockIdx.x;

    // global-load mapping
    const int aRow = tid >> 1;             // 0..127
    const int aCol = (tid & 1) * 4;        // 0 or 4
    const int bRow = tid >> 5;             // 0..7
    const int bCol = (tid & 31) * 4;       // 0..124

    // compute mapping: 16x16 thread grid of 8x8 tiles
    const int ty = tid >> 4;               // 0..15
    const int tx = tid & 15;               // 0..15

    const float* Ab = A + (size_t)(brow * GBM) * K;
    const float* Bb = Bm + bcol * GBN;

    float acc[GTM][GTN];
#pragma unroll
    for (int i = 0; i < GTM; i++)
#pragma unroll
        for (int j = 0; j < GTN; j++) acc[i][j] = 0.f;

    for (int kt = 0; kt < K; kt += GBK) {
        float4 a4 = *(const float4*)(Ab + (size_t)aRow * K + kt + aCol);
        sA[aCol + 0][aRow] = a4.x;
        sA[aCol + 1][aRow] = a4.y;
        sA[aCol + 2][aRow] = a4.z;
        sA[aCol + 3][aRow] = a4.w;
        float4 b4 = *(const float4*)(Bb + (size_t)(kt + bRow) * N + bCol);
        *(float4*)&sB[bRow][bCol] = b4;
        __syncthreads();

#pragma unroll
        for (int k = 0; k < GBK; k++) {
            float ar[GTM], br[GTN];
            *(float4*)&ar[0] = *(const float4*)&sA[k][ty * GTM + 0];
            *(float4*)&ar[4] = *(const float4*)&sA[k][ty * GTM + 4];
            *(float4*)&br[0] = *(const float4*)&sB[k][tx * GTN + 0];
            *(float4*)&br[4] = *(const float4*)&sB[k][tx * GTN + 4];
#pragma unroll
            for (int i = 0; i < GTM; i++)
#pragma unroll
                for (int j = 0; j < GTN; j++)
                    acc[i][j] += ar[i] * br[j];
        }
        __syncthreads();
    }

    // epilogue: bias add + store
    float br0[GTN];
#pragma unroll
    for (int j = 0; j < GTN; j++) br0[j] = bias[bcol * GBN + tx * GTN + j];

    float* Cb = C + (size_t)(brow * GBM) * N + bcol * GBN;
#pragma unroll
    for (int i = 0; i < GTM; i++) {
        const int r = ty * GTM + i;
#pragma unroll
        for (int j = 0; j < GTN; j += 4) {
            const int c = tx * GTN + j;
            float4 v;
            v.x = acc[i][j + 0] + br0[j + 0];
            v.y = acc[i][j + 1] + br0[j + 1];
            v.z = acc[i][j + 2] + br0[j + 2];
            v.w = acc[i][j + 3] + br0[j + 3];
            *(float4*)(Cb + (size_t)r * N + c) = v;
        }
    }
}

// ---------------------------------------------------------------------------
// Pool K/V: level l0 in 0..3, stride s = 8<<l0, avg over s raw timesteps.
// grid = (480, 128), block = 64. x: pooled-row index across levels; y: bh.
// ---------------------------------------------------------------------------
__global__ void pool_kv(const float* __restrict__ qkv,
                        float* __restrict__ kp, float* __restrict__ vp)
{
    const int r  = blockIdx.x;     // 0..479
    const int bh = blockIdx.y;     // 0..127
    const int dd = threadIdx.x;    // 0..63

    int l0, pi;
    if      (r < 256) { l0 = 0; pi = r;       }
    else if (r < 384) { l0 = 1; pi = r - 256; }
    else if (r < 448) { l0 = 2; pi = r - 384; }
    else              { l0 = 3; pi = r - 448; }
    const int nl = 256 >> l0;
    const int s  = 8 << l0;

    const int b = bh >> 4, h = bh & 15;
    const size_t base = (size_t)b * T_SZ * C3 + h * DH + dd;
    const size_t kb = base + C_SZ;
    const size_t vb = base + 2 * C_SZ;

    float sk = 0.f, sv = 0.f;
    const int t0 = pi * s;
    for (int i = 0; i < s; i++) {
        sk += qkv[kb + (size_t)(t0 + i) * C3];
        sv += qkv[vb + (size_t)(t0 + i) * C3];
    }
    const float inv = 1.f / (float)s;
    const size_t o = POOL_OFF[l0] + ((size_t)bh * nl + pi) * DH + dd;
    kp[o] = sk * inv;
    vp[o] = sv * inv;
}

// ---------------------------------------------------------------------------
// Fused MLA attention. One CTA per (64-query block, bh).
// Dynamic smem layout (floats):
//   sQ [64*65]  scaled queries
//   sK [128*65] fine K window (then reused for V window)
//   sP [32*65]  pooled K (4 levels x 8) (then reused for pooled V)
//   sS [64*97]  scores -> normalized attention weights
// ---------------------------------------------------------------------------
#define SQ_OFF 0
#define SK_OFF (64 * 65)
#define SP_OFF (SK_OFF + 128 * 65)
#define SS_OFF (SP_OFF + 32 * 65)
#define ATTN_SMEM_FLOATS (SS_OFF + 64 * 97)
#define ATTN_SMEM_BYTES  (ATTN_SMEM_FLOATS * 4)   // 83,072 B

__global__ __launch_bounds__(256, 1)
void mla_attn(const float* __restrict__ qkv,
              const float* __restrict__ kpool,
              const float* __restrict__ vpool,
              float* __restrict__ o)
{
    extern __shared__ float sm[];
    float* sQ = sm + SQ_OFF;
    float* sK = sm + SK_OFF;
    float* sP = sm + SP_OFF;
    float* sS = sm + SS_OFF;

    const int qb  = blockIdx.x;    // 0..31  query block (64 queries)
    const int bh  = blockIdx.y;    // 0..127
    const int b   = bh >> 4, h = bh & 15;
    const int tid = threadIdx.x;   // 256

    const size_t baseQ = (size_t)b * T_SZ * C3 + h * DH;
    const size_t baseK = baseQ + C_SZ;
    const size_t baseV = baseQ + 2 * C_SZ;

    // --- load Q (pre-scaled by 1/sqrt(64) = 1/8) ---
    for (int i = tid; i < 64 * 64; i += 256) {
        const int r = i >> 6, dd = i & 63;
        const int t = qb * MW + r;
        sQ[r * 65 + dd] = qkv[baseQ + (size_t)t * C3 + dd] * 0.125f;
    }
    // --- load fine K window: rows 0..63 = prev block (zeros for qb==0) ---
    for (int i = tid; i < 128 * 64; i += 256) {
        const int r = i >> 6, dd = i & 63;
        const int t = qb * MW - MW + r;
        sK[r * 65 + dd] = (t >= 0) ? qkv[baseK + (size_t)t * C3 + dd] : 0.f;
    }
    // --- load pooled K of the previous coarse block per level ---
    for (int i = tid; i < 32 * 64; i += 256) {
        const int r = i >> 6, dd = i & 63;     // r = l0*8 + idx
        const int l0 = r >> 3, idx = r & 7;
        const int cb = (qb >> l0) - 1;
        float v = 0.f;
        if (cb >= 0) {
            const int nl = 256 >> l0;
            v = kpool[POOL_OFF[l0] + ((size_t)bh * nl + cb * PP + idx) * DH + dd];
        }
        sP[r * 65 + dd] = v;
    }
    __syncthreads();

    // --- scores: 64 queries x (64 fine + 32 coarse) ---
    for (int e = tid; e < 64 * 96; e += 256) {
        const int q = e / 96, j = e - q * 96;
        const float* qr = &sQ[q * 65];
        const float* kr = (j < 64) ? &sK[(q + 1 + j) * 65] : &sP[(j - 64) * 65];
        float s = 0.f;
#pragma unroll
        for (int dd = 0; dd < 64; dd++) s += qr[dd] * kr[dd];
        sS[q * 97 + j] = s;
    }
    __syncthreads();

    // --- overwrite sK/sP with V (same indexing) ---
    for (int i = tid; i < 128 * 64; i += 256) {
        const int r = i >> 6, dd = i & 63;
        const int t = qb * MW - MW + r;
        sK[r * 65 + dd] = (t >= 0) ? qkv[baseV + (size_t)t * C3 + dd] : 0.f;
    }
    for (int i = tid; i < 32 * 64; i += 256) {
        const int r = i >> 6, dd = i & 63;
        const int l0 = r >> 3, idx = r & 7;
        const int cb = (qb >> l0) - 1;
        float v = 0.f;
        if (cb >= 0) {
            const int nl = 256 >> l0;
            v = vpool[POOL_OFF[l0] + ((size_t)bh * nl + cb * PP + idx) * DH + dd];
        }
        sP[r * 65 + dd] = v;
    }

    // --- cross-level softmax: one thread per query (threads 0..63) ---
    if (tid < 64) {
        float* row = &sS[tid * 97];
        float mx0 = -1e30f;
#pragma unroll
        for (int j = 0; j < 64; j++) mx0 = fmaxf(mx0, row[j]);
        float mn = mx0;
#pragma unroll
        for (int l = 0; l < NLEV; l++) {
            float mxl = -1e30f;
#pragma unroll
            for (int i = 0; i < PP; i++) mxl = fmaxf(mxl, row[64 + l * PP + i]);
            mn = fminf(mn, mxl);
        }
        float esum = 0.f;
#pragma unroll
        for (int j = 0; j < 64; j++) {
            const float e = __expf(row[j] - mn);
            row[j] = e;
            esum += e;
        }
        const float scl[NLEV] = {8.f, 16.f, 32.f, 64.f};
#pragma unroll
        for (int l = 0; l < NLEV; l++)
#pragma unroll
            for (int i = 0; i < PP; i++) {
                const float e = __expf(row[64 + l * PP + i] - mn) * scl[l];
                row[64 + l * PP + i] = e;
                esum += e;
            }
        const float inv = 1.f / esum;
#pragma unroll
        for (int j = 0; j < 96; j++) row[j] *= inv;
    }
    __syncthreads();

    // --- stage 2: out[q][dd] = C_row . V ---
    const int dd = tid & 63;
    const int q0 = tid >> 6;               // 0..3
    for (int qi = q0; qi < 64; qi += 4) {
        const float* row = &sS[qi * 97];
        float acc = 0.f;
#pragma unroll
        for (int j = 0; j < 64; j++) acc += row[j] * sK[(qi + 1 + j) * 65 + dd];
#pragma unroll
        for (int j = 0; j < 32; j++) acc += row[64 + j] * sP[j * 65 + dd];
        const int t = qb * MW + qi;
        o[((size_t)b * T_SZ + t) * C_SZ + h * DH + dd] = acc;
    }
}

// ---------------------------------------------------------------------------
// Launch
// ---------------------------------------------------------------------------
extern "C" void kernel_launch(void* const* d_in, const int* in_sizes, int n_in,
                              void* d_out, int out_size)
{
    (void)in_sizes; (void)n_in; (void)out_size;
    const float* x      = (const float*)d_in[0];
    const float* W_attn = (const float*)d_in[1];
    const float* b_attn = (const float*)d_in[2];
    const float* W_proj = (const float*)d_in[3];
    const float* b_proj = (const float*)d_in[4];
    float* out = (float*)d_out;

    float *qkv, *attn, *kp, *vp;
    cudaGetSymbolAddress((void**)&qkv,  g_qkv);
    cudaGetSymbolAddress((void**)&attn, g_attn);
    cudaGetSymbolAddress((void**)&kp,   g_kpool);
    cudaGetSymbolAddress((void**)&vp,   g_vpool);

    cudaFuncSetAttribute(mla_attn, cudaFuncAttributeMaxDynamicSharedMemorySize,
                         ATTN_SMEM_BYTES);

    // 1) qkv = x @ W_attn + b_attn
    sgemm_bias<<<dim3(C3 / GBN, M_ROWS / GBM), 256>>>(
        x, W_attn, b_attn, qkv, M_ROWS, C3, C_SZ);

    // 2) pooled K/V (4 levels)
    pool_kv<<<dim3(480, BH), 64>>>(qkv, kp, vp);

    // 3) fused MLA attention -> [B,T,C] layout
    mla_attn<<<dim3(T_SZ / MW, BH), 256, ATTN_SMEM_BYTES>>>(qkv, kp, vp, attn);

    // 4) out = attn @ W_proj + b_proj
    sgemm_bias<<<dim3(C_SZ / GBN, M_ROWS / GBM), 256>>>(
        attn, W_proj, b_proj, out, M_ROWS, C_SZ, C_SZ);
}

// round 4
// speedup vs baseline: 2.8746x; 2.8746x over previous
#include <cuda_runtime.h>
#include <cuda_fp16.h>
#include <cstdint>

// ---------------------------------------------------------------------------
// Problem constants
// ---------------------------------------------------------------------------
#define B_SZ   8
#define T_SZ   2048
#define C_SZ   1024
#define H_SZ   16
#define DH     64
#define BH     (B_SZ * H_SZ)     // 128
#define C3     (3 * C_SZ)        // 3072
#define M_ROWS (B_SZ * T_SZ)     // 16384
#define MW     64
#define PP     8
#define NLEV   4

__device__ __constant__ size_t POOL_OFF[4] = {
    0,
    (size_t)BH * 256 * DH,
    (size_t)BH * 256 * DH + (size_t)BH * 128 * DH,
    (size_t)BH * 256 * DH + (size_t)BH * 128 * DH + (size_t)BH * 64 * DH
};
#define POOL_TOTAL ((size_t)BH * (256 + 128 + 64 + 32) * DH)

// ---------------------------------------------------------------------------
// Scratch (static device allocations; no cudaMalloc anywhere)
// ---------------------------------------------------------------------------
__device__ float  g_qkv   [(size_t)M_ROWS * C3];     // 201 MB (fp32 for attention accuracy)
__device__ __half g_x_h   [(size_t)M_ROWS * C_SZ];   //  32 MB  x in fp16
__device__ __half g_attn_h[(size_t)M_ROWS * C_SZ];   //  32 MB  attention out in fp16
__device__ float  g_kpool [POOL_TOTAL];
__device__ float  g_vpool [POOL_TOTAL];
__device__ __half g_wt_attn[(size_t)C3 * C_SZ];      //   6 MB  W_attn^T [3072,1024] fp16
__device__ __half g_wt_proj[(size_t)C_SZ * C_SZ];    //   2 MB  W_proj^T [1024,1024] fp16

// ===========================================================================
// PTX helpers (sm_100-safe set: cp.async / ldmatrix / mma.sync)
// ===========================================================================
__device__ __forceinline__ uint32_t smem_u32(const void* p) {
    uint32_t a;
    asm("{ .reg .u64 t; cvta.to.shared.u64 t, %1; cvt.u32.u64 %0, t; }" : "=r"(a) : "l"(p));
    return a;
}
__device__ __forceinline__ void cp_async16(uint32_t saddr, const void* g) {
    asm volatile("cp.async.cg.shared.global [%0], [%1], 16;" :: "r"(saddr), "l"(g));
}
__device__ __forceinline__ void cp_commit() {
    asm volatile("cp.async.commit_group;" ::: "memory");
}
template <int N>
__device__ __forceinline__ void cp_wait() {
    asm volatile("cp.async.wait_group %0;" :: "n"(N) : "memory");
}
__device__ __forceinline__ void ldm_x4(uint32_t& r0, uint32_t& r1, uint32_t& r2,
                                       uint32_t& r3, uint32_t addr) {
    asm volatile("ldmatrix.sync.aligned.m8n8.x4.shared.b16 {%0,%1,%2,%3}, [%4];"
                 : "=r"(r0), "=r"(r1), "=r"(r2), "=r"(r3) : "r"(addr));
}
__device__ __forceinline__ void mma16816(float* d, const uint32_t* a, const uint32_t* b) {
    asm volatile(
        "mma.sync.aligned.m16n8k16.row.col.f32.f16.f16.f32 "
        "{%0,%1,%2,%3}, {%4,%5,%6,%7}, {%8,%9}, {%0,%1,%2,%3};"
        : "+f"(d[0]), "+f"(d[1]), "+f"(d[2]), "+f"(d[3])
        : "r"(a[0]), "r"(a[1]), "r"(a[2]), "r"(a[3]), "r"(b[0]), "r"(b[1]));
}

// ===========================================================================
// Prep kernels: fp32->fp16 convert, and weight transpose+convert
// ===========================================================================
__global__ void convert_f2h(const float* __restrict__ in, __half* __restrict__ out,
                            size_t n)
{
    const size_t i = ((size_t)blockIdx.x * blockDim.x + threadIdx.x) * 4;
    if (i < n) {
        float4 v = *(const float4*)(in + i);
        __half2 h0 = __floats2half2_rn(v.x, v.y);
        __half2 h1 = __floats2half2_rn(v.z, v.w);
        *(__half2*)(out + i)     = h0;
        *(__half2*)(out + i + 2) = h1;
    }
}

// W [K][N] fp32 -> Wt [N][K] fp16
__global__ void transpose_kh(const float* __restrict__ W, __half* __restrict__ Wt,
                             int K, int N)
{
    __shared__ float t[32][33];
    const int x = blockIdx.x * 32 + threadIdx.x;   // N index
    const int y = blockIdx.y * 32 + threadIdx.y;   // K index
#pragma unroll
    for (int j = 0; j < 32; j += 8)
        t[threadIdx.y + j][threadIdx.x] = W[(size_t)(y + j) * N + x];
    __syncthreads();
    const int xo = blockIdx.y * 32 + threadIdx.x;  // K index
    const int yo = blockIdx.x * 32 + threadIdx.y;  // N index
#pragma unroll
    for (int j = 0; j < 32; j += 8)
        Wt[(size_t)(yo + j) * K + xo] = __float2half(t[threadIdx.x][threadIdx.y + j]);
}

// ===========================================================================
// HGEMM (fp16 in, fp32 accum): C[M,N] = A[M,K] @ Bt[N,K]^T + bias
// Tile 128x128x32, 3-stage cp.async, mma.sync m16n8k16.
// 8 warps: 2(M) x 4(N); warp tile 64x32.
// ===========================================================================
#define HBM_T 128
#define HBN_T 128
#define HBK_T 32
#define HSTAGES 3
#define HPITCH 80                                    // bytes per 32-half row (bank-safe)
#define HSTAGE_BYTES (2 * 128 * HPITCH)              // A + B = 20480
#define HGEMM_SMEM (HSTAGES * HSTAGE_BYTES)          // 61440

__global__ __launch_bounds__(256)
void hgemm_bias(const __half* __restrict__ Ah, const __half* __restrict__ Bh,
                const float* __restrict__ bias, float* __restrict__ C,
                int M, int N, int K)
{
    extern __shared__ char smem[];
    const uint32_t sb = smem_u32(smem);
    const int tid  = threadIdx.x;
    const int wid  = tid >> 5;
    const int lane = tid & 31;

    const int row0 = blockIdx.y * HBM_T;
    const int col0 = blockIdx.x * HBN_T;
    const int m0   = (wid & 1) * 64;      // warp M origin in tile
    const int n0   = (wid >> 1) * 32;     // warp N origin in tile
    const int NT   = K / HBK_T;

    // ldmatrix per-lane address components
    const int mat = lane >> 3, li = lane & 7;
    const int rowA = (mat & 1) * 8 + li;              // A: mat0/2 rows m.., mat1/3 m+8
    const int kA   = (mat >> 1) * 8;                  // A: mat2/3 k+8
    const int rowB = (mat >> 1) * 8 + li;             // B: mat2/3 n+8
    const int kB   = (mat & 1) * 8;                   // B: mat1/3 k+8

    float acc[4][4][4];
#pragma unroll
    for (int i = 0; i < 4; i++)
#pragma unroll
        for (int j = 0; j < 4; j++)
#pragma unroll
            for (int r = 0; r < 4; r++) acc[i][j][r] = 0.f;

    auto load_tile = [&](int t) {
        const uint32_t sA = sb + (t % HSTAGES) * HSTAGE_BYTES;
        const uint32_t sB = sA + 128 * HPITCH;
        const int k0 = t * HBK_T;
#pragma unroll
        for (int i = 0; i < 2; i++) {
            const int id = i * 256 + tid;             // 0..511
            const int r = id >> 2, c = id & 3;
            cp_async16(sA + r * HPITCH + c * 16, Ah + (size_t)(row0 + r) * K + k0 + c * 8);
        }
#pragma unroll
        for (int i = 0; i < 2; i++) {
            const int id = i * 256 + tid;
            const int r = id >> 2, c = id & 3;
            cp_async16(sB + r * HPITCH + c * 16, Bh + (size_t)(col0 + r) * K + k0 + c * 8);
        }
    };

    // prologue
    for (int t = 0; t < HSTAGES - 1; t++) { load_tile(t); cp_commit(); }

    for (int kt = 0; kt < NT; kt++) {
        cp_wait<HSTAGES - 2>();
        __syncthreads();
        const int pf = kt + HSTAGES - 1;
        if (pf < NT) load_tile(pf);
        cp_commit();

        const uint32_t sA = sb + (kt % HSTAGES) * HSTAGE_BYTES;
        const uint32_t sB = sA + 128 * HPITCH;
#pragma unroll
        for (int kc = 0; kc < 2; kc++) {
            uint32_t af[4][4], bf[2][4];
#pragma unroll
            for (int mt = 0; mt < 4; mt++)
                ldm_x4(af[mt][0], af[mt][1], af[mt][2], af[mt][3],
                       sA + (m0 + mt * 16 + rowA) * HPITCH + (kc * 16 + kA) * 2);
#pragma unroll
            for (int np = 0; np < 2; np++)
                ldm_x4(bf[np][0], bf[np][1], bf[np][2], bf[np][3],
                       sB + (n0 + np * 16 + rowB) * HPITCH + (kc * 16 + kB) * 2);
#pragma unroll
            for (int mt = 0; mt < 4; mt++)
#pragma unroll
                for (int nt = 0; nt < 4; nt++)
                    mma16816(acc[mt][nt], af[mt], &bf[nt >> 1][(nt & 1) * 2]);
        }
    }
    cp_wait<0>();

    // epilogue: regs -> gmem with bias (full 32B sectors per quarter-warp)
#pragma unroll
    for (int mt = 0; mt < 4; mt++) {
#pragma unroll
        for (int nt = 0; nt < 4; nt++) {
            const int r  = row0 + m0 + mt * 16 + (lane >> 2);
            const int cc = col0 + n0 + nt * 8 + (lane & 3) * 2;
            const float b0 = bias[cc], b1 = bias[cc + 1];
            float2 v0 = { acc[mt][nt][0] + b0, acc[mt][nt][1] + b1 };
            float2 v1 = { acc[mt][nt][2] + b0, acc[mt][nt][3] + b1 };
            *(float2*)(C + (size_t)r * N + cc)       = v0;
            *(float2*)(C + (size_t)(r + 8) * N + cc) = v1;
        }
    }
}

// ---------------------------------------------------------------------------
// Pool K/V (unchanged)
// ---------------------------------------------------------------------------
__global__ void pool_kv(const float* __restrict__ qkv,
                        float* __restrict__ kp, float* __restrict__ vp)
{
    const int r  = blockIdx.x;
    const int bh = blockIdx.y;
    const int dd = threadIdx.x;

    int l0, pi;
    if      (r < 256) { l0 = 0; pi = r;       }
    else if (r < 384) { l0 = 1; pi = r - 256; }
    else if (r < 448) { l0 = 2; pi = r - 384; }
    else              { l0 = 3; pi = r - 448; }
    const int nl = 256 >> l0;
    const int s  = 8 << l0;

    const int b = bh >> 4, h = bh & 15;
    const size_t base = (size_t)b * T_SZ * C3 + h * DH + dd;
    const size_t kb = base + C_SZ;
    const size_t vb = base + 2 * C_SZ;

    float sk = 0.f, sv = 0.f;
    const int t0 = pi * s;
    for (int i = 0; i < s; i++) {
        sk += qkv[kb + (size_t)(t0 + i) * C3];
        sv += qkv[vb + (size_t)(t0 + i) * C3];
    }
    const float inv = 1.f / (float)s;
    const size_t o = POOL_OFF[l0] + ((size_t)bh * nl + pi) * DH + dd;
    kp[o] = sk * inv;
    vp[o] = sv * inv;
}

// ---------------------------------------------------------------------------
// Fused MLA attention (outputs fp16 for GEMM2)
// ---------------------------------------------------------------------------
#define SQ_OFF 0
#define SK_OFF (64 * 65)
#define SP_OFF (SK_OFF + 128 * 65)
#define SS_OFF (SP_OFF + 32 * 65)
#define ATTN_SMEM_FLOATS (SS_OFF + 64 * 97)
#define ATTN_SMEM_BYTES  (ATTN_SMEM_FLOATS * 4)

__global__ __launch_bounds__(256, 1)
void mla_attn(const float* __restrict__ qkv,
              const float* __restrict__ kpool,
              const float* __restrict__ vpool,
              __half* __restrict__ o)
{
    extern __shared__ float sm[];
    float* sQ = sm + SQ_OFF;
    float* sK = sm + SK_OFF;
    float* sP = sm + SP_OFF;
    float* sS = sm + SS_OFF;

    const int qb  = blockIdx.x;
    const int bh  = blockIdx.y;
    const int b   = bh >> 4, h = bh & 15;
    const int tid = threadIdx.x;

    const size_t baseQ = (size_t)b * T_SZ * C3 + h * DH;
    const size_t baseK = baseQ + C_SZ;
    const size_t baseV = baseQ + 2 * C_SZ;

    for (int i = tid; i < 64 * 64; i += 256) {
        const int r = i >> 6, dd = i & 63;
        const int t = qb * MW + r;
        sQ[r * 65 + dd] = qkv[baseQ + (size_t)t * C3 + dd] * 0.125f;
    }
    for (int i = tid; i < 128 * 64; i += 256) {
        const int r = i >> 6, dd = i & 63;
        const int t = qb * MW - MW + r;
        sK[r * 65 + dd] = (t >= 0) ? qkv[baseK + (size_t)t * C3 + dd] : 0.f;
    }
    for (int i = tid; i < 32 * 64; i += 256) {
        const int r = i >> 6, dd = i & 63;
        const int l0 = r >> 3, idx = r & 7;
        const int cb = (qb >> l0) - 1;
        float v = 0.f;
        if (cb >= 0) {
            const int nl = 256 >> l0;
            v = kpool[POOL_OFF[l0] + ((size_t)bh * nl + cb * PP + idx) * DH + dd];
        }
        sP[r * 65 + dd] = v;
    }
    __syncthreads();

    for (int e = tid; e < 64 * 96; e += 256) {
        const int q = e / 96, j = e - q * 96;
        const float* qr = &sQ[q * 65];
        const float* kr = (j < 64) ? &sK[(q + 1 + j) * 65] : &sP[(j - 64) * 65];
        float s = 0.f;
#pragma unroll
        for (int dd = 0; dd < 64; dd++) s += qr[dd] * kr[dd];
        sS[q * 97 + j] = s;
    }
    __syncthreads();

    for (int i = tid; i < 128 * 64; i += 256) {
        const int r = i >> 6, dd = i & 63;
        const int t = qb * MW - MW + r;
        sK[r * 65 + dd] = (t >= 0) ? qkv[baseV + (size_t)t * C3 + dd] : 0.f;
    }
    for (int i = tid; i < 32 * 64; i += 256) {
        const int r = i >> 6, dd = i & 63;
        const int l0 = r >> 3, idx = r & 7;
        const int cb = (qb >> l0) - 1;
        float v = 0.f;
        if (cb >= 0) {
            const int nl = 256 >> l0;
            v = vpool[POOL_OFF[l0] + ((size_t)bh * nl + cb * PP + idx) * DH + dd];
        }
        sP[r * 65 + dd] = v;
    }

    if (tid < 64) {
        float* row = &sS[tid * 97];
        float mx0 = -1e30f;
#pragma unroll
        for (int j = 0; j < 64; j++) mx0 = fmaxf(mx0, row[j]);
        float mn = mx0;
#pragma unroll
        for (int l = 0; l < NLEV; l++) {
            float mxl = -1e30f;
#pragma unroll
            for (int i = 0; i < PP; i++) mxl = fmaxf(mxl, row[64 + l * PP + i]);
            mn = fminf(mn, mxl);
        }
        float esum = 0.f;
#pragma unroll
        for (int j = 0; j < 64; j++) {
            const float e = __expf(row[j] - mn);
            row[j] = e;
            esum += e;
        }
        const float scl[NLEV] = {8.f, 16.f, 32.f, 64.f};
#pragma unroll
        for (int l = 0; l < NLEV; l++)
#pragma unroll
            for (int i = 0; i < PP; i++) {
                const float e = __expf(row[64 + l * PP + i] - mn) * scl[l];
                row[64 + l * PP + i] = e;
                esum += e;
            }
        const float inv = 1.f / esum;
#pragma unroll
        for (int j = 0; j < 96; j++) row[j] *= inv;
    }
    __syncthreads();

    const int dd = tid & 63;
    const int q0 = tid >> 6;
    for (int qi = q0; qi < 64; qi += 4) {
        const float* row = &sS[qi * 97];
        float acc = 0.f;
#pragma unroll
        for (int j = 0; j < 64; j++) acc += row[j] * sK[(qi + 1 + j) * 65 + dd];
#pragma unroll
        for (int j = 0; j < 32; j++) acc += row[64 + j] * sP[j * 65 + dd];
        const int t = qb * MW + qi;
        o[((size_t)b * T_SZ + t) * C_SZ + h * DH + dd] = __float2half(acc);
    }
}

// ---------------------------------------------------------------------------
// Launch
// ---------------------------------------------------------------------------
extern "C" void kernel_launch(void* const* d_in, const int* in_sizes, int n_in,
                              void* d_out, int out_size)
{
    (void)in_sizes; (void)n_in; (void)out_size;
    const float* x      = (const float*)d_in[0];
    const float* W_attn = (const float*)d_in[1];
    const float* b_attn = (const float*)d_in[2];
    const float* W_proj = (const float*)d_in[3];
    const float* b_proj = (const float*)d_in[4];
    float* out = (float*)d_out;

    float  *qkv, *kp, *vp;
    __half *xh, *ah, *wta, *wtp;
    cudaGetSymbolAddress((void**)&qkv, g_qkv);
    cudaGetSymbolAddress((void**)&xh,  g_x_h);
    cudaGetSymbolAddress((void**)&ah,  g_attn_h);
    cudaGetSymbolAddress((void**)&kp,  g_kpool);
    cudaGetSymbolAddress((void**)&vp,  g_vpool);
    cudaGetSymbolAddress((void**)&wta, g_wt_attn);
    cudaGetSymbolAddress((void**)&wtp, g_wt_proj);

    cudaFuncSetAttribute(mla_attn, cudaFuncAttributeMaxDynamicSharedMemorySize,
                         ATTN_SMEM_BYTES);
    cudaFuncSetAttribute(hgemm_bias, cudaFuncAttributeMaxDynamicSharedMemorySize,
                         HGEMM_SMEM);

    // 0) prep: x -> fp16; weights -> transposed fp16 [N,K]
    const size_t nx = (size_t)M_ROWS * C_SZ;
    convert_f2h<<<(unsigned)((nx / 4 + 255) / 256), 256>>>(x, xh, nx);
    transpose_kh<<<dim3(C3 / 32, C_SZ / 32), dim3(32, 8)>>>(W_attn, wta, C_SZ, C3);
    transpose_kh<<<dim3(C_SZ / 32, C_SZ / 32), dim3(32, 8)>>>(W_proj, wtp, C_SZ, C_SZ);

    // 1) qkv = x @ W_attn + b_attn  (tensor cores, fp16 in / fp32 accum)
    hgemm_bias<<<dim3(C3 / HBN_T, M_ROWS / HBM_T), 256, HGEMM_SMEM>>>(
        xh, wta, b_attn, qkv, M_ROWS, C3, C_SZ);

    // 2) pooled K/V
    pool_kv<<<dim3(480, BH), 64>>>(qkv, kp, vp);

    // 3) fused MLA attention -> fp16 [B,T,C]
    mla_attn<<<dim3(T_SZ / MW, BH), 256, ATTN_SMEM_BYTES>>>(qkv, kp, vp, ah);

    // 4) out = attn @ W_proj + b_proj
    hgemm_bias<<<dim3(C_SZ / HBN_T, M_ROWS / HBM_T), 256, HGEMM_SMEM>>>(
        ah, wtp, b_proj, out, M_ROWS, C_SZ, C_SZ);
}

// round 5
// speedup vs baseline: 3.6750x; 1.2784x over previous
#include <cuda_runtime.h>
#include <cuda_fp16.h>
#include <cstdint>

// ---------------------------------------------------------------------------
// Problem constants
// ---------------------------------------------------------------------------
#define B_SZ   8
#define T_SZ   2048
#define C_SZ   1024
#define H_SZ   16
#define DH     64
#define BH     (B_SZ * H_SZ)     // 128
#define C3     (3 * C_SZ)        // 3072
#define M_ROWS (B_SZ * T_SZ)     // 16384
#define MW     64
#define PP     8
#define NLEV   4

__device__ __constant__ size_t POOL_OFF[4] = {
    0,
    (size_t)BH * 256 * DH,
    (size_t)BH * 256 * DH + (size_t)BH * 128 * DH,
    (size_t)BH * 256 * DH + (size_t)BH * 128 * DH + (size_t)BH * 64 * DH
};
#define POOL_TOTAL ((size_t)BH * (256 + 128 + 64 + 32) * DH)

// ---------------------------------------------------------------------------
// Scratch (static device allocations; no cudaMalloc anywhere)
// ---------------------------------------------------------------------------
__device__ float  g_qkv   [(size_t)M_ROWS * C3];     // 201 MB fp32
__device__ __half g_x_h   [(size_t)M_ROWS * C_SZ];
__device__ __half g_attn_h[(size_t)M_ROWS * C_SZ];
__device__ float  g_kpool [POOL_TOTAL];
__device__ float  g_vpool [POOL_TOTAL];
__device__ __half g_wt_attn[(size_t)C3 * C_SZ];
__device__ __half g_wt_proj[(size_t)C_SZ * C_SZ];

// ===========================================================================
// PTX helpers
// ===========================================================================
__device__ __forceinline__ uint32_t smem_u32(const void* p) {
    uint32_t a;
    asm("{ .reg .u64 t; cvta.to.shared.u64 t, %1; cvt.u32.u64 %0, t; }" : "=r"(a) : "l"(p));
    return a;
}
__device__ __forceinline__ void cp_async16(uint32_t saddr, const void* g) {
    asm volatile("cp.async.cg.shared.global [%0], [%1], 16;" :: "r"(saddr), "l"(g));
}
__device__ __forceinline__ void cp_commit() {
    asm volatile("cp.async.commit_group;" ::: "memory");
}
template <int N>
__device__ __forceinline__ void cp_wait() {
    asm volatile("cp.async.wait_group %0;" :: "n"(N) : "memory");
}
__device__ __forceinline__ void ldm_x4(uint32_t& r0, uint32_t& r1, uint32_t& r2,
                                       uint32_t& r3, uint32_t addr) {
    asm volatile("ldmatrix.sync.aligned.m8n8.x4.shared.b16 {%0,%1,%2,%3}, [%4];"
                 : "=r"(r0), "=r"(r1), "=r"(r2), "=r"(r3) : "r"(addr));
}
__device__ __forceinline__ void mma16816(float* d, const uint32_t* a, const uint32_t* b) {
    asm volatile(
        "mma.sync.aligned.m16n8k16.row.col.f32.f16.f16.f32 "
        "{%0,%1,%2,%3}, {%4,%5,%6,%7}, {%8,%9}, {%0,%1,%2,%3};"
        : "+f"(d[0]), "+f"(d[1]), "+f"(d[2]), "+f"(d[3])
        : "r"(a[0]), "r"(a[1]), "r"(a[2]), "r"(a[3]), "r"(b[0]), "r"(b[1]));
}

// ===========================================================================
// Prep kernels
// ===========================================================================
__global__ void convert_f2h(const float* __restrict__ in, __half* __restrict__ out,
                            size_t n)
{
    const size_t i = ((size_t)blockIdx.x * blockDim.x + threadIdx.x) * 4;
    if (i < n) {
        float4 v = *(const float4*)(in + i);
        *(__half2*)(out + i)     = __floats2half2_rn(v.x, v.y);
        *(__half2*)(out + i + 2) = __floats2half2_rn(v.z, v.w);
    }
}

// W [K][N] fp32 -> Wt [N][K] fp16
__global__ void transpose_kh(const float* __restrict__ W, __half* __restrict__ Wt,
                             int K, int N)
{
    __shared__ float t[32][33];
    const int x = blockIdx.x * 32 + threadIdx.x;
    const int y = blockIdx.y * 32 + threadIdx.y;
#pragma unroll
    for (int j = 0; j < 32; j += 8)
        t[threadIdx.y + j][threadIdx.x] = W[(size_t)(y + j) * N + x];
    __syncthreads();
    const int xo = blockIdx.y * 32 + threadIdx.x;
    const int yo = blockIdx.x * 32 + threadIdx.y;
#pragma unroll
    for (int j = 0; j < 32; j += 8)
        Wt[(size_t)(yo + j) * K + xo] = __float2half(t[threadIdx.x][threadIdx.y + j]);
}

// ===========================================================================
// HGEMM (fp16 in, fp32 accum): C[M,N] = A[M,K] @ Bt[N,K]^T + bias
// Tile 128x256x32, 3-stage cp.async, warp tile 64x64.
// ===========================================================================
#define HBM_T 128
#define HBN_T 256
#define HBK_T 32
#define HSTAGES 3
#define HPITCH 80                                       // bytes per 32-half row
#define HSTAGE_BYTES ((HBM_T + HBN_T) * HPITCH)         // 30720
#define HGEMM_SMEM (HSTAGES * HSTAGE_BYTES)             // 92160

__global__ __launch_bounds__(256)
void hgemm_bias(const __half* __restrict__ Ah, const __half* __restrict__ Bh,
                const float* __restrict__ bias, float* __restrict__ C,
                int M, int N, int K)
{
    extern __shared__ char smem[];
    const uint32_t sb = smem_u32(smem);
    const int tid  = threadIdx.x;
    const int wid  = tid >> 5;
    const int lane = tid & 31;

    const int row0 = blockIdx.y * HBM_T;
    const int col0 = blockIdx.x * HBN_T;
    const int m0   = (wid & 1) * 64;
    const int n0   = (wid >> 1) * 64;
    const int NT   = K / HBK_T;

    const int mat = lane >> 3, li = lane & 7;
    const int rowA = (mat & 1) * 8 + li;
    const int kA   = (mat >> 1) * 8;
    const int rowB = (mat >> 1) * 8 + li;
    const int kB   = (mat & 1) * 8;

    float acc[4][8][4];
#pragma unroll
    for (int i = 0; i < 4; i++)
#pragma unroll
        for (int j = 0; j < 8; j++)
#pragma unroll
            for (int r = 0; r < 4; r++) acc[i][j][r] = 0.f;

    auto load_tile = [&](int t) {
        const uint32_t sA = sb + (t % HSTAGES) * HSTAGE_BYTES;
        const uint32_t sB = sA + HBM_T * HPITCH;
        const int k0 = t * HBK_T;
#pragma unroll
        for (int i = 0; i < 2; i++) {                    // A: 512 chunks
            const int id = i * 256 + tid;
            const int r = id >> 2, c = id & 3;
            cp_async16(sA + r * HPITCH + c * 16, Ah + (size_t)(row0 + r) * K + k0 + c * 8);
        }
#pragma unroll
        for (int i = 0; i < 4; i++) {                    // B: 1024 chunks
            const int id = i * 256 + tid;
            const int r = id >> 2, c = id & 3;
            cp_async16(sB + r * HPITCH + c * 16, Bh + (size_t)(col0 + r) * K + k0 + c * 8);
        }
    };

    for (int t = 0; t < HSTAGES - 1; t++) { load_tile(t); cp_commit(); }

    for (int kt = 0; kt < NT; kt++) {
        cp_wait<HSTAGES - 2>();
        __syncthreads();
        const int pf = kt + HSTAGES - 1;
        if (pf < NT) load_tile(pf);
        cp_commit();

        const uint32_t sA = sb + (kt % HSTAGES) * HSTAGE_BYTES;
        const uint32_t sB = sA + HBM_T * HPITCH;
#pragma unroll
        for (int kc = 0; kc < 2; kc++) {
            uint32_t af[4][4], bf[4][4];
#pragma unroll
            for (int mt = 0; mt < 4; mt++)
                ldm_x4(af[mt][0], af[mt][1], af[mt][2], af[mt][3],
                       sA + (m0 + mt * 16 + rowA) * HPITCH + (kc * 16 + kA) * 2);
#pragma unroll
            for (int np = 0; np < 4; np++)
                ldm_x4(bf[np][0], bf[np][1], bf[np][2], bf[np][3],
                       sB + (n0 + np * 16 + rowB) * HPITCH + (kc * 16 + kB) * 2);
#pragma unroll
            for (int mt = 0; mt < 4; mt++)
#pragma unroll
                for (int nt = 0; nt < 8; nt++)
                    mma16816(acc[mt][nt], af[mt], &bf[nt >> 1][(nt & 1) * 2]);
        }
    }
    cp_wait<0>();

#pragma unroll
    for (int mt = 0; mt < 4; mt++) {
#pragma unroll
        for (int nt = 0; nt < 8; nt++) {
            const int r  = row0 + m0 + mt * 16 + (lane >> 2);
            const int cc = col0 + n0 + nt * 8 + (lane & 3) * 2;
            const float b0 = bias[cc], b1 = bias[cc + 1];
            float2 v0 = { acc[mt][nt][0] + b0, acc[mt][nt][1] + b1 };
            float2 v1 = { acc[mt][nt][2] + b0, acc[mt][nt][3] + b1 };
            *(float2*)(C + (size_t)r * N + cc)       = v0;
            *(float2*)(C + (size_t)(r + 8) * N + cc) = v1;
        }
    }
}

// ---------------------------------------------------------------------------
// Pool level 0 (stride 8): read raw K/V once.
// grid (8, 128bh), block 256. Each CTA: 32 pooled rows x 64 dd.
// ---------------------------------------------------------------------------
__global__ void pool0(const float* __restrict__ qkv,
                      float* __restrict__ kp, float* __restrict__ vp)
{
    const int bh = blockIdx.y;
    const int b = bh >> 4, h = bh & 15;
    const size_t kb = (size_t)b * T_SZ * C3 + h * DH + C_SZ;
    const size_t vb = kb + C_SZ;

    for (int idx = threadIdx.x; idx < 32 * 64; idx += 256) {
        const int pi = blockIdx.x * 32 + (idx >> 6);
        const int dd = idx & 63;
        float sk = 0.f, sv = 0.f;
        const int t0 = pi * 8;
#pragma unroll
        for (int i = 0; i < 8; i++) {
            sk += qkv[kb + (size_t)(t0 + i) * C3 + dd];
            sv += qkv[vb + (size_t)(t0 + i) * C3 + dd];
        }
        const size_t o = ((size_t)bh * 256 + pi) * DH + dd;
        kp[o] = sk * 0.125f;
        vp[o] = sv * 0.125f;
    }
}

// ---------------------------------------------------------------------------
// Pool levels 1..3 hierarchically: level l = avg of 2 entries of level l-1.
// grid 128bh, block 256.
// ---------------------------------------------------------------------------
__global__ void pool_rest(float* __restrict__ kp, float* __restrict__ vp)
{
    const int bh = blockIdx.x;
    for (int l = 1; l <= 3; l++) {
        const int nl = 256 >> l;
        const size_t src = POOL_OFF[l - 1] + (size_t)bh * (nl * 2) * DH;
        const size_t dst = POOL_OFF[l]     + (size_t)bh * nl * DH;
        for (int idx = threadIdx.x; idx < nl * 64; idx += 256) {
            const int pi = idx >> 6, dd = idx & 63;
            kp[dst + (size_t)pi * DH + dd] =
                0.5f * (kp[src + (size_t)(2 * pi) * DH + dd] +
                        kp[src + (size_t)(2 * pi + 1) * DH + dd]);
            vp[dst + (size_t)pi * DH + dd] =
                0.5f * (vp[src + (size_t)(2 * pi) * DH + dd] +
                        vp[src + (size_t)(2 * pi + 1) * DH + dd]);
        }
        __syncthreads();   // level l visible to whole CTA before level l+1
    }
}

// ---------------------------------------------------------------------------
// Fused MLA attention, register-tiled + float4 vectorized.
// smem: sQ[64][68], sKP[160][68] (K then V), sS[64][164]
// ---------------------------------------------------------------------------
#define SQP 68
#define SKPP 68
#define SSP 164
#define SKP_OFF (64 * SQP)
#define SS_OFF  (SKP_OFF + 160 * SKPP)
#define ATTN_FLOATS (SS_OFF + 64 * SSP)
#define ATTN_BYTES  (ATTN_FLOATS * 4)     // 102,912 B

__global__ __launch_bounds__(256, 2)
void mla_attn(const float* __restrict__ qkv,
              const float* __restrict__ kpool,
              const float* __restrict__ vpool,
              __half* __restrict__ o)
{
    extern __shared__ float sm[];
    float* sQ  = sm;
    float* sKP = sm + SKP_OFF;
    float* sS  = sm + SS_OFF;

    const int qb  = blockIdx.x;     // 0..31
    const int bh  = blockIdx.y;     // 0..127
    const int b   = bh >> 4, h = bh & 15;
    const int tid = threadIdx.x;

    const size_t baseQ = (size_t)b * T_SZ * C3 + h * DH;
    const size_t baseK = baseQ + C_SZ;
    const size_t baseV = baseQ + 2 * C_SZ;

    // --- load Q (scaled) ---
    for (int i = tid; i < 64 * 16; i += 256) {
        const int r = i >> 4, c = (i & 15) * 4;
        float4 v = *(const float4*)(qkv + baseQ + (size_t)(qb * MW + r) * C3 + c);
        v.x *= 0.125f; v.y *= 0.125f; v.z *= 0.125f; v.w *= 0.125f;
        *(float4*)&sQ[r * SQP + c] = v;
    }
    // --- load K: rows 0..127 fine window, 128..159 coarse ---
    for (int i = tid; i < 160 * 16; i += 256) {
        const int r = i >> 4, c = (i & 15) * 4;
        float4 v = {0.f, 0.f, 0.f, 0.f};
        if (r < 128) {
            const int t = qb * MW - MW + r;
            if (t >= 0) v = *(const float4*)(qkv + baseK + (size_t)t * C3 + c);
        } else {
            const int rr = r - 128, l0 = rr >> 3, ix = rr & 7;
            const int cb = (qb >> l0) - 1;
            if (cb >= 0) {
                const int nl = 256 >> l0;
                v = *(const float4*)(kpool + POOL_OFF[l0] +
                                     ((size_t)bh * nl + cb * PP + ix) * DH + c);
            }
        }
        *(float4*)&sKP[r * SKPP + c] = v;
    }
    __syncthreads();

    // --- scores: full 64x160 GEMM, 4q x 10t register tile ---
    {
        const int ty4  = (tid >> 4) * 4;
        const int tx10 = (tid & 15) * 10;
        float acc[4][10];
#pragma unroll
        for (int i = 0; i < 4; i++)
#pragma unroll
            for (int j = 0; j < 10; j++) acc[i][j] = 0.f;
        for (int d = 0; d < 64; d += 4) {
            float4 a[4], bb[10];
#pragma unroll
            for (int i = 0; i < 4; i++)
                a[i] = *(float4*)&sQ[(ty4 + i) * SQP + d];
#pragma unroll
            for (int j = 0; j < 10; j++)
                bb[j] = *(float4*)&sKP[(tx10 + j) * SKPP + d];
#pragma unroll
            for (int i = 0; i < 4; i++)
#pragma unroll
                for (int j = 0; j < 10; j++) {
                    acc[i][j] += a[i].x * bb[j].x;
                    acc[i][j] += a[i].y * bb[j].y;
                    acc[i][j] += a[i].z * bb[j].z;
                    acc[i][j] += a[i].w * bb[j].w;
                }
        }
#pragma unroll
        for (int i = 0; i < 4; i++)
#pragma unroll
            for (int j = 0; j < 10; j++)
                sS[(ty4 + i) * SSP + tx10 + j] = acc[i][j];
    }
    __syncthreads();

    // --- reload sKP with V (independent of sS) ---
    for (int i = tid; i < 160 * 16; i += 256) {
        const int r = i >> 4, c = (i & 15) * 4;
        float4 v = {0.f, 0.f, 0.f, 0.f};
        if (r < 128) {
            const int t = qb * MW - MW + r;
            if (t >= 0) v = *(const float4*)(qkv + baseV + (size_t)t * C3 + c);
        } else {
            const int rr = r - 128, l0 = rr >> 3, ix = rr & 7;
            const int cb = (qb >> l0) - 1;
            if (cb >= 0) {
                const int nl = 256 >> l0;
                v = *(const float4*)(vpool + POOL_OFF[l0] +
                                     ((size_t)bh * nl + cb * PP + ix) * DH + c);
            }
        }
        *(float4*)&sKP[r * SKPP + c] = v;
    }

    // --- cross-level softmax with band masking: 4 threads per query ---
    {
        const int qi = tid >> 2, sub = tid & 3;
        float* row = sS + qi * SSP;
        const int lo = qi + 1, hi = qi + 64;
        const int j0 = sub * 32;

        float mx = -1e30f;
#pragma unroll
        for (int j = 0; j < 32; j++) {
            const int t = j0 + j;
            if (t >= lo && t <= hi) mx = fmaxf(mx, row[t]);
        }
        mx = fmaxf(mx, __shfl_xor_sync(0xffffffffu, mx, 1));
        mx = fmaxf(mx, __shfl_xor_sync(0xffffffffu, mx, 2));

        float mc = -1e30f;
#pragma unroll
        for (int i = 0; i < 8; i++) mc = fmaxf(mc, row[128 + sub * 8 + i]);
        float mcm = fminf(mc, __shfl_xor_sync(0xffffffffu, mc, 1));
        mcm = fminf(mcm, __shfl_xor_sync(0xffffffffu, mcm, 2));
        const float mn = fminf(mx, mcm);

        float es = 0.f;
#pragma unroll
        for (int j = 0; j < 32; j++) {
            const int t = j0 + j;
            float e = 0.f;
            if (t >= lo && t <= hi) { e = __expf(row[t] - mn); es += e; }
            row[t] = e;
        }
        const float scl = (float)(8 << sub);
#pragma unroll
        for (int i = 0; i < 8; i++) {
            const float e = __expf(row[128 + sub * 8 + i] - mn) * scl;
            row[128 + sub * 8 + i] = e;
            es += e;
        }
        es += __shfl_xor_sync(0xffffffffu, es, 1);
        es += __shfl_xor_sync(0xffffffffu, es, 2);
        const float inv = 1.f / es;
#pragma unroll
        for (int j = 0; j < 32; j++) row[j0 + j] *= inv;
#pragma unroll
        for (int i = 0; i < 8; i++) row[128 + sub * 8 + i] *= inv;
    }
    __syncthreads();

    // --- stage 2: out(64x64) = S(64x160) @ V(160x64), 4q x 4dd tile ---
    {
        const int ty4 = (tid >> 4) * 4;
        const int tx4 = (tid & 15) * 4;
        float acc[4][4];
#pragma unroll
        for (int i = 0; i < 4; i++)
#pragma unroll
            for (int j = 0; j < 4; j++) acc[i][j] = 0.f;
        for (int t = 0; t < 160; t += 4) {
            float4 a[4], bb[4];
#pragma unroll
            for (int i = 0; i < 4; i++)
                a[i] = *(float4*)&sS[(ty4 + i) * SSP + t];
#pragma unroll
            for (int r = 0; r < 4; r++)
                bb[r] = *(float4*)&sKP[(t + r) * SKPP + tx4];
#pragma unroll
            for (int i = 0; i < 4; i++) {
                acc[i][0] += a[i].x * bb[0].x + a[i].y * bb[1].x
                           + a[i].z * bb[2].x + a[i].w * bb[3].x;
                acc[i][1] += a[i].x * bb[0].y + a[i].y * bb[1].y
                           + a[i].z * bb[2].y + a[i].w * bb[3].y;
                acc[i][2] += a[i].x * bb[0].z + a[i].y * bb[1].z
                           + a[i].z * bb[2].z + a[i].w * bb[3].z;
                acc[i][3] += a[i].x * bb[0].w + a[i].y * bb[1].w
                           + a[i].z * bb[2].w + a[i].w * bb[3].w;
            }
        }
#pragma unroll
        for (int i = 0; i < 4; i++) {
            const int tq = qb * MW + ty4 + i;
            __half2* dst = (__half2*)(o + ((size_t)b * T_SZ + tq) * C_SZ + h * DH + tx4);
            dst[0] = __floats2half2_rn(acc[i][0], acc[i][1]);
            dst[1] = __floats2half2_rn(acc[i][2], acc[i][3]);
        }
    }
}

// ---------------------------------------------------------------------------
// Launch
// ---------------------------------------------------------------------------
extern "C" void kernel_launch(void* const* d_in, const int* in_sizes, int n_in,
                              void* d_out, int out_size)
{
    (void)in_sizes; (void)n_in; (void)out_size;
    const float* x      = (const float*)d_in[0];
    const float* W_attn = (const float*)d_in[1];
    const float* b_attn = (const float*)d_in[2];
    const float* W_proj = (const float*)d_in[3];
    const float* b_proj = (const float*)d_in[4];
    float* out = (float*)d_out;

    float  *qkv, *kp, *vp;
    __half *xh, *ah, *wta, *wtp;
    cudaGetSymbolAddress((void**)&qkv, g_qkv);
    cudaGetSymbolAddress((void**)&xh,  g_x_h);
    cudaGetSymbolAddress((void**)&ah,  g_attn_h);
    cudaGetSymbolAddress((void**)&kp,  g_kpool);
    cudaGetSymbolAddress((void**)&vp,  g_vpool);
    cudaGetSymbolAddress((void**)&wta, g_wt_attn);
    cudaGetSymbolAddress((void**)&wtp, g_wt_proj);

    cudaFuncSetAttribute(mla_attn, cudaFuncAttributeMaxDynamicSharedMemorySize,
                         ATTN_BYTES);
    cudaFuncSetAttribute(hgemm_bias, cudaFuncAttributeMaxDynamicSharedMemorySize,
                         HGEMM_SMEM);

    // 0) prep
    const size_t nx = (size_t)M_ROWS * C_SZ;
    convert_f2h<<<(unsigned)((nx / 4 + 255) / 256), 256>>>(x, xh, nx);
    transpose_kh<<<dim3(C3 / 32, C_SZ / 32), dim3(32, 8)>>>(W_attn, wta, C_SZ, C3);
    transpose_kh<<<dim3(C_SZ / 32, C_SZ / 32), dim3(32, 8)>>>(W_proj, wtp, C_SZ, C_SZ);

    // 1) qkv = x @ W_attn + b_attn
    hgemm_bias<<<dim3(C3 / HBN_T, M_ROWS / HBM_T), 256, HGEMM_SMEM>>>(
        xh, wta, b_attn, qkv, M_ROWS, C3, C_SZ);

    // 2) pooled K/V (hierarchical)
    pool0<<<dim3(8, BH), 256>>>(qkv, kp, vp);
    pool_rest<<<BH, 256>>>(kp, vp);

    // 3) fused MLA attention -> fp16 [B,T,C]
    mla_attn<<<dim3(T_SZ / MW, BH), 256, ATTN_BYTES>>>(qkv, kp, vp, ah);

    // 4) out = attn @ W_proj + b_proj
    hgemm_bias<<<dim3(C_SZ / HBN_T, M_ROWS / HBM_T), 256, HGEMM_SMEM>>>(
        ah, wtp, b_proj, out, M_ROWS, C_SZ, C_SZ);
}

// round 7
// speedup vs baseline: 5.1657x; 1.4056x over previous
#include <cuda_runtime.h>
#include <cuda_fp16.h>
#include <cstdint>

// ---------------------------------------------------------------------------
// Problem constants
// ---------------------------------------------------------------------------
#define B_SZ   8
#define T_SZ   2048
#define C_SZ   1024
#define H_SZ   16
#define DH     64
#define BH     (B_SZ * H_SZ)     // 128
#define C3     (3 * C_SZ)        // 3072
#define M_ROWS (B_SZ * T_SZ)     // 16384
#define MW     64
#define PP     8
#define NLEV   4

__device__ __constant__ size_t POOL_OFF[4] = {
    0,
    (size_t)BH * 256 * DH,
    (size_t)BH * 256 * DH + (size_t)BH * 128 * DH,
    (size_t)BH * 256 * DH + (size_t)BH * 128 * DH + (size_t)BH * 64 * DH
};
#define POOL_TOTAL ((size_t)BH * (256 + 128 + 64 + 32) * DH)

// ---------------------------------------------------------------------------
// Scratch (static device allocations)
// ---------------------------------------------------------------------------
__device__ float  g_qkv   [(size_t)M_ROWS * C3];
__device__ __half g_x_h   [(size_t)M_ROWS * C_SZ];
__device__ __half g_attn_h[(size_t)M_ROWS * C_SZ];
__device__ float  g_kpool [POOL_TOTAL];
__device__ float  g_vpool [POOL_TOTAL];
__device__ __half g_wt_attn[(size_t)C3 * C_SZ];
__device__ __half g_wt_proj[(size_t)C_SZ * C_SZ];

// ===========================================================================
// PTX helpers
// ===========================================================================
__device__ __forceinline__ uint32_t smem_u32(const void* p) {
    uint32_t a;
    asm("{ .reg .u64 t; cvta.to.shared.u64 t, %1; cvt.u32.u64 %0, t; }" : "=r"(a) : "l"(p));
    return a;
}
__device__ __forceinline__ uint32_t h2_bits(__half2 v) {
    return *reinterpret_cast<uint32_t*>(&v);
}
__device__ __forceinline__ void cp_async16(uint32_t saddr, const void* g) {
    asm volatile("cp.async.cg.shared.global [%0], [%1], 16;" :: "r"(saddr), "l"(g));
}
__device__ __forceinline__ void cp_commit() {
    asm volatile("cp.async.commit_group;" ::: "memory");
}
template <int N>
__device__ __forceinline__ void cp_wait() {
    asm volatile("cp.async.wait_group %0;" :: "n"(N) : "memory");
}
__device__ __forceinline__ void ldm_x4(uint32_t& r0, uint32_t& r1, uint32_t& r2,
                                       uint32_t& r3, uint32_t addr) {
    asm volatile("ldmatrix.sync.aligned.m8n8.x4.shared.b16 {%0,%1,%2,%3}, [%4];"
                 : "=r"(r0), "=r"(r1), "=r"(r2), "=r"(r3) : "r"(addr));
}
__device__ __forceinline__ void ldm_x4t(uint32_t& r0, uint32_t& r1, uint32_t& r2,
                                        uint32_t& r3, uint32_t addr) {
    asm volatile("ldmatrix.sync.aligned.m8n8.x4.trans.shared.b16 {%0,%1,%2,%3}, [%4];"
                 : "=r"(r0), "=r"(r1), "=r"(r2), "=r"(r3) : "r"(addr));
}
__device__ __forceinline__ void mma16816(float* d, const uint32_t* a, const uint32_t* b) {
    asm volatile(
        "mma.sync.aligned.m16n8k16.row.col.f32.f16.f16.f32 "
        "{%0,%1,%2,%3}, {%4,%5,%6,%7}, {%8,%9}, {%0,%1,%2,%3};"
        : "+f"(d[0]), "+f"(d[1]), "+f"(d[2]), "+f"(d[3])
        : "r"(a[0]), "r"(a[1]), "r"(a[2]), "r"(a[3]), "r"(b[0]), "r"(b[1]));
}

// ===========================================================================
// Prep kernels
// ===========================================================================
__global__ void convert_f2h(const float* __restrict__ in, __half* __restrict__ out,
                            size_t n)
{
    const size_t i = ((size_t)blockIdx.x * blockDim.x + threadIdx.x) * 4;
    if (i < n) {
        float4 v = *(const float4*)(in + i);
        *(__half2*)(out + i)     = __floats2half2_rn(v.x, v.y);
        *(__half2*)(out + i + 2) = __floats2half2_rn(v.z, v.w);
    }
}

__global__ void transpose_kh(const float* __restrict__ W, __half* __restrict__ Wt,
                             int K, int N)
{
    __shared__ float t[32][33];
    const int x = blockIdx.x * 32 + threadIdx.x;
    const int y = blockIdx.y * 32 + threadIdx.y;
#pragma unroll
    for (int j = 0; j < 32; j += 8)
        t[threadIdx.y + j][threadIdx.x] = W[(size_t)(y + j) * N + x];
    __syncthreads();
    const int xo = blockIdx.y * 32 + threadIdx.x;
    const int yo = blockIdx.x * 32 + threadIdx.y;
#pragma unroll
    for (int j = 0; j < 32; j += 8)
        Wt[(size_t)(yo + j) * K + xo] = __float2half(t[threadIdx.x][threadIdx.y + j]);
}

// ===========================================================================
// HGEMM: round-4 shape (128x128x32, warp 64x32), 4-stage cp.async.
// ===========================================================================
#define HBM_T 128
#define HBN_T 128
#define HBK_T 32
#define HSTAGES 4
#define HPITCH 80
#define HSTAGE_BYTES (2 * 128 * HPITCH)                 // 20480
#define HGEMM_SMEM (HSTAGES * HSTAGE_BYTES)             // 81920

__global__ __launch_bounds__(256)
void hgemm_bias(const __half* __restrict__ Ah, const __half* __restrict__ Bh,
                const float* __restrict__ bias, float* __restrict__ C,
                int M, int N, int K)
{
    extern __shared__ char smem[];
    const uint32_t sb = smem_u32(smem);
    const int tid  = threadIdx.x;
    const int wid  = tid >> 5;
    const int lane = tid & 31;

    const int row0 = blockIdx.y * HBM_T;
    const int col0 = blockIdx.x * HBN_T;
    const int m0   = (wid & 1) * 64;
    const int n0   = (wid >> 1) * 32;
    const int NT   = K / HBK_T;

    const int mat = lane >> 3, li = lane & 7;
    const int rowA = (mat & 1) * 8 + li;
    const int kA   = (mat >> 1) * 8;
    const int rowB = (mat >> 1) * 8 + li;
    const int kB   = (mat & 1) * 8;

    float acc[4][4][4];
#pragma unroll
    for (int i = 0; i < 4; i++)
#pragma unroll
        for (int j = 0; j < 4; j++)
#pragma unroll
            for (int r = 0; r < 4; r++) acc[i][j][r] = 0.f;

    auto load_tile = [&](int t) {
        const uint32_t sA = sb + (t % HSTAGES) * HSTAGE_BYTES;
        const uint32_t sB = sA + 128 * HPITCH;
        const int k0 = t * HBK_T;
#pragma unroll
        for (int i = 0; i < 2; i++) {
            const int id = i * 256 + tid;
            const int r = id >> 2, c = id & 3;
            cp_async16(sA + r * HPITCH + c * 16, Ah + (size_t)(row0 + r) * K + k0 + c * 8);
        }
#pragma unroll
        for (int i = 0; i < 2; i++) {
            const int id = i * 256 + tid;
            const int r = id >> 2, c = id & 3;
            cp_async16(sB + r * HPITCH + c * 16, Bh + (size_t)(col0 + r) * K + k0 + c * 8);
        }
    };

    for (int t = 0; t < HSTAGES - 1; t++) { load_tile(t); cp_commit(); }

    for (int kt = 0; kt < NT; kt++) {
        cp_wait<HSTAGES - 2>();
        __syncthreads();
        const int pf = kt + HSTAGES - 1;
        if (pf < NT) load_tile(pf);
        cp_commit();

        const uint32_t sA = sb + (kt % HSTAGES) * HSTAGE_BYTES;
        const uint32_t sB = sA + 128 * HPITCH;
#pragma unroll
        for (int kc = 0; kc < 2; kc++) {
            uint32_t af[4][4], bf[2][4];
#pragma unroll
            for (int mt = 0; mt < 4; mt++)
                ldm_x4(af[mt][0], af[mt][1], af[mt][2], af[mt][3],
                       sA + (m0 + mt * 16 + rowA) * HPITCH + (kc * 16 + kA) * 2);
#pragma unroll
            for (int np = 0; np < 2; np++)
                ldm_x4(bf[np][0], bf[np][1], bf[np][2], bf[np][3],
                       sB + (n0 + np * 16 + rowB) * HPITCH + (kc * 16 + kB) * 2);
#pragma unroll
            for (int mt = 0; mt < 4; mt++)
#pragma unroll
                for (int nt = 0; nt < 4; nt++)
                    mma16816(acc[mt][nt], af[mt], &bf[nt >> 1][(nt & 1) * 2]);
        }
    }
    cp_wait<0>();

#pragma unroll
    for (int mt = 0; mt < 4; mt++) {
#pragma unroll
        for (int nt = 0; nt < 4; nt++) {
            const int r  = row0 + m0 + mt * 16 + (lane >> 2);
            const int cc = col0 + n0 + nt * 8 + (lane & 3) * 2;
            const float b0 = bias[cc], b1 = bias[cc + 1];
            float2 v0 = { acc[mt][nt][0] + b0, acc[mt][nt][1] + b1 };
            float2 v1 = { acc[mt][nt][2] + b0, acc[mt][nt][3] + b1 };
            *(float2*)(C + (size_t)r * N + cc)       = v0;
            *(float2*)(C + (size_t)(r + 8) * N + cc) = v1;
        }
    }
}

// ---------------------------------------------------------------------------
// Pooling (hierarchical)
// ---------------------------------------------------------------------------
__global__ void pool0(const float* __restrict__ qkv,
                      float* __restrict__ kp, float* __restrict__ vp)
{
    const int bh = blockIdx.y;
    const int b = bh >> 4, h = bh & 15;
    const size_t kb = (size_t)b * T_SZ * C3 + h * DH + C_SZ;
    const size_t vb = kb + C_SZ;

    for (int idx = threadIdx.x; idx < 32 * 64; idx += 256) {
        const int pi = blockIdx.x * 32 + (idx >> 6);
        const int dd = idx & 63;
        float sk = 0.f, sv = 0.f;
        const int t0 = pi * 8;
#pragma unroll
        for (int i = 0; i < 8; i++) {
            sk += qkv[kb + (size_t)(t0 + i) * C3 + dd];
            sv += qkv[vb + (size_t)(t0 + i) * C3 + dd];
        }
        const size_t o = ((size_t)bh * 256 + pi) * DH + dd;
        kp[o] = sk * 0.125f;
        vp[o] = sv * 0.125f;
    }
}

__global__ void pool_rest(float* __restrict__ kp, float* __restrict__ vp)
{
    const int bh = blockIdx.x;
    for (int l = 1; l <= 3; l++) {
        const int nl = 256 >> l;
        const size_t src = POOL_OFF[l - 1] + (size_t)bh * (nl * 2) * DH;
        const size_t dst = POOL_OFF[l]     + (size_t)bh * nl * DH;
        for (int idx = threadIdx.x; idx < nl * 64; idx += 256) {
            const int pi = idx >> 6, dd = idx & 63;
            kp[dst + (size_t)pi * DH + dd] =
                0.5f * (kp[src + (size_t)(2 * pi) * DH + dd] +
                        kp[src + (size_t)(2 * pi + 1) * DH + dd]);
            vp[dst + (size_t)pi * DH + dd] =
                0.5f * (vp[src + (size_t)(2 * pi) * DH + dd] +
                        vp[src + (size_t)(2 * pi + 1) * DH + dd]);
        }
        __syncthreads();
    }
}

// ---------------------------------------------------------------------------
// Fused MLA attention — tensor-core version.
// smem (bytes): sQh fp16 [64][72]   @ 0       (9216)
//               sKh fp16 [160][72]  @ 9216    (23040)  K, then V
//               sS  fp32 [64][164]  @ 32256   (41984)
//               sWh fp16 [64][168]  @ 74240   (21504)
// ---------------------------------------------------------------------------
#define AQH 0
#define AKH 9216
#define ASS 32256
#define AWH 74240
#define ATTN2_BYTES 95744
#define QP  72      // halves
#define KP  72
#define SP  164     // floats
#define WP  168     // halves

__global__ __launch_bounds__(256, 2)
void mla_attn(const float* __restrict__ qkv,
              const float* __restrict__ kpool,
              const float* __restrict__ vpool,
              __half* __restrict__ o)
{
    extern __shared__ char smem[];
    const uint32_t sb = smem_u32(smem);
    float* sS = (float*)(smem + ASS);
    __half* sWh = (__half*)(smem + AWH);

    const int qb  = blockIdx.x;
    const int bh  = blockIdx.y;
    const int b   = bh >> 4, h = bh & 15;
    const int tid = threadIdx.x;
    const int wid = tid >> 5;
    const int lane = tid & 31;

    const size_t baseQ = (size_t)b * T_SZ * C3 + h * DH;
    const size_t baseK = baseQ + C_SZ;
    const size_t baseV = baseQ + 2 * C_SZ;

    const int mat = lane >> 3, li = lane & 7;
    const int rowA = (mat & 1) * 8 + li;
    const int kA   = (mat >> 1) * 8;
    const int rowB = (mat >> 1) * 8 + li;
    const int kB   = (mat & 1) * 8;

    // --- load Q (scaled) -> fp16 ---
    for (int i = tid; i < 64 * 16; i += 256) {
        const int r = i >> 4, c = (i & 15) * 4;
        float4 v = *(const float4*)(qkv + baseQ + (size_t)(qb * MW + r) * C3 + c);
        uint2 hv;
        hv.x = h2_bits(__floats2half2_rn(v.x * 0.125f, v.y * 0.125f));
        hv.y = h2_bits(__floats2half2_rn(v.z * 0.125f, v.w * 0.125f));
        *(uint2*)(smem + AQH + r * (QP * 2) + c * 2) = hv;
    }
    // --- load K (fine 128 + coarse 32) -> fp16 ---
    for (int i = tid; i < 160 * 16; i += 256) {
        const int r = i >> 4, c = (i & 15) * 4;
        float4 v = {0.f, 0.f, 0.f, 0.f};
        if (r < 128) {
            const int t = qb * MW - MW + r;
            if (t >= 0) v = *(const float4*)(qkv + baseK + (size_t)t * C3 + c);
        } else {
            const int rr = r - 128, l0 = rr >> 3, ix = rr & 7;
            const int cb = (qb >> l0) - 1;
            if (cb >= 0) {
                const int nl = 256 >> l0;
                v = *(const float4*)(kpool + POOL_OFF[l0] +
                                     ((size_t)bh * nl + cb * PP + ix) * DH + c);
            }
        }
        uint2 hv;
        hv.x = h2_bits(__floats2half2_rn(v.x, v.y));
        hv.y = h2_bits(__floats2half2_rn(v.z, v.w));
        *(uint2*)(smem + AKH + r * (KP * 2) + c * 2) = hv;
    }
    __syncthreads();

    // --- scores: warp tile 16q x 80t, k=64 ---
    {
        const int q16   = (wid & 3) * 16;
        const int thalf = (wid >> 2) * 80;
        float acc[10][4];
#pragma unroll
        for (int f = 0; f < 10; f++)
#pragma unroll
            for (int r = 0; r < 4; r++) acc[f][r] = 0.f;
#pragma unroll
        for (int ks = 0; ks < 4; ks++) {
            const int k0 = ks * 16;
            uint32_t a[4];
            ldm_x4(a[0], a[1], a[2], a[3],
                   sb + AQH + (q16 + rowA) * (QP * 2) + (k0 + kA) * 2);
            uint32_t bk[5][4];
#pragma unroll
            for (int np = 0; np < 5; np++)
                ldm_x4(bk[np][0], bk[np][1], bk[np][2], bk[np][3],
                       sb + AKH + (thalf + np * 16 + rowB) * (KP * 2) + (k0 + kB) * 2);
#pragma unroll
            for (int f = 0; f < 10; f++)
                mma16816(acc[f], a, &bk[f >> 1][(f & 1) * 2]);
        }
#pragma unroll
        for (int f = 0; f < 10; f++) {
            const int n = thalf + f * 8 + (lane & 3) * 2;
            const int r = q16 + (lane >> 2);
            *(float2*)&sS[r * SP + n]       = { acc[f][0], acc[f][1] };
            *(float2*)&sS[(r + 8) * SP + n] = { acc[f][2], acc[f][3] };
        }
    }
    __syncthreads();

    // --- overwrite sKh with V ---
    for (int i = tid; i < 160 * 16; i += 256) {
        const int r = i >> 4, c = (i & 15) * 4;
        float4 v = {0.f, 0.f, 0.f, 0.f};
        if (r < 128) {
            const int t = qb * MW - MW + r;
            if (t >= 0) v = *(const float4*)(qkv + baseV + (size_t)t * C3 + c);
        } else {
            const int rr = r - 128, l0 = rr >> 3, ix = rr & 7;
            const int cb = (qb >> l0) - 1;
            if (cb >= 0) {
                const int nl = 256 >> l0;
                v = *(const float4*)(vpool + POOL_OFF[l0] +
                                     ((size_t)bh * nl + cb * PP + ix) * DH + c);
            }
        }
        uint2 hv;
        hv.x = h2_bits(__floats2half2_rn(v.x, v.y));
        hv.y = h2_bits(__floats2half2_rn(v.z, v.w));
        *(uint2*)(smem + AKH + r * (KP * 2) + c * 2) = hv;
    }

    // --- cross-level softmax (fp32), write fp16 weights to sWh ---
    {
        const int qi = tid >> 2, sub = tid & 3;
        float* row = sS + qi * SP;
        __half* wrow = sWh + qi * WP;
        const int lo = qi + 1, hi = qi + 64;
        const int j0 = sub * 32;

        float mx = -1e30f;
#pragma unroll
        for (int j = 0; j < 32; j++) {
            const int t = j0 + j;
            if (t >= lo && t <= hi) mx = fmaxf(mx, row[t]);
        }
        mx = fmaxf(mx, __shfl_xor_sync(0xffffffffu, mx, 1));
        mx = fmaxf(mx, __shfl_xor_sync(0xffffffffu, mx, 2));

        float mc = -1e30f;
#pragma unroll
        for (int i = 0; i < 8; i++) mc = fmaxf(mc, row[128 + sub * 8 + i]);
        float mcm = fminf(mc, __shfl_xor_sync(0xffffffffu, mc, 1));
        mcm = fminf(mcm, __shfl_xor_sync(0xffffffffu, mcm, 2));
        const float mn = fminf(mx, mcm);

        float es = 0.f;
        float ef[32], ec[8];
#pragma unroll
        for (int j = 0; j < 32; j++) {
            const int t = j0 + j;
            float e = 0.f;
            if (t >= lo && t <= hi) { e = __expf(row[t] - mn); es += e; }
            ef[j] = e;
        }
        const float scl = (float)(8 << sub);
#pragma unroll
        for (int i = 0; i < 8; i++) {
            const float e = __expf(row[128 + sub * 8 + i] - mn) * scl;
            ec[i] = e;
            es += e;
        }
        es += __shfl_xor_sync(0xffffffffu, es, 1);
        es += __shfl_xor_sync(0xffffffffu, es, 2);
        const float inv = 1.f / es;
#pragma unroll
        for (int j = 0; j < 32; j++) wrow[j0 + j] = __float2half(ef[j] * inv);
#pragma unroll
        for (int i = 0; i < 8; i++) wrow[128 + sub * 8 + i] = __float2half(ec[i] * inv);
    }
    __syncthreads();

    // --- stage 2: O(64x64) = W(64x160) @ V(160x64); warp tile 16q x 32d ---
    {
        const int q16 = (wid & 3) * 16;
        const int d0  = (wid >> 2) * 32;
        float acc[4][4];
#pragma unroll
        for (int f = 0; f < 4; f++)
#pragma unroll
            for (int r = 0; r < 4; r++) acc[f][r] = 0.f;
#pragma unroll
        for (int ks = 0; ks < 10; ks++) {
            const int t0 = ks * 16;
            uint32_t a[4];
            ldm_x4(a[0], a[1], a[2], a[3],
                   sb + AWH + (q16 + rowA) * (WP * 2) + (t0 + kA) * 2);
            uint32_t bv[2][4];
#pragma unroll
            for (int g = 0; g < 2; g++)
                ldm_x4t(bv[g][0], bv[g][1], bv[g][2], bv[g][3],
                        sb + AKH + (t0 + (lane & 15)) * (KP * 2)
                           + (d0 + g * 16 + ((lane >> 4) << 3)) * 2);
#pragma unroll
            for (int f = 0; f < 4; f++)
                mma16816(acc[f], a, &bv[f >> 1][(f & 1) * 2]);
        }
#pragma unroll
        for (int f = 0; f < 4; f++) {
            const int col = d0 + f * 8 + (lane & 3) * 2;
            const int r0  = q16 + (lane >> 2);
            const int tq0 = qb * MW + r0;
            __half2 v0 = __floats2half2_rn(acc[f][0], acc[f][1]);
            __half2 v1 = __floats2half2_rn(acc[f][2], acc[f][3]);
            *(__half2*)(o + ((size_t)b * T_SZ + tq0) * C_SZ + h * DH + col)     = v0;
            *(__half2*)(o + ((size_t)b * T_SZ + tq0 + 8) * C_SZ + h * DH + col) = v1;
        }
    }
}

// ---------------------------------------------------------------------------
// Launch
// ---------------------------------------------------------------------------
extern "C" void kernel_launch(void* const* d_in, const int* in_sizes, int n_in,
                              void* d_out, int out_size)
{
    (void)in_sizes; (void)n_in; (void)out_size;
    const float* x      = (const float*)d_in[0];
    const float* W_attn = (const float*)d_in[1];
    const float* b_attn = (const float*)d_in[2];
    const float* W_proj = (const float*)d_in[3];
    const float* b_proj = (const float*)d_in[4];
    float* out = (float*)d_out;

    float  *qkv, *kp, *vp;
    __half *xh, *ah, *wta, *wtp;
    cudaGetSymbolAddress((void**)&qkv, g_qkv);
    cudaGetSymbolAddress((void**)&xh,  g_x_h);
    cudaGetSymbolAddress((void**)&ah,  g_attn_h);
    cudaGetSymbolAddress((void**)&kp,  g_kpool);
    cudaGetSymbolAddress((void**)&vp,  g_vpool);
    cudaGetSymbolAddress((void**)&wta, g_wt_attn);
    cudaGetSymbolAddress((void**)&wtp, g_wt_proj);

    cudaFuncSetAttribute(mla_attn, cudaFuncAttributeMaxDynamicSharedMemorySize,
                         ATTN2_BYTES);
    cudaFuncSetAttribute(hgemm_bias, cudaFuncAttributeMaxDynamicSharedMemorySize,
                         HGEMM_SMEM);

    // 0) prep
    const size_t nx = (size_t)M_ROWS * C_SZ;
    convert_f2h<<<(unsigned)((nx / 4 + 255) / 256), 256>>>(x, xh, nx);
    transpose_kh<<<dim3(C3 / 32, C_SZ / 32), dim3(32, 8)>>>(W_attn, wta, C_SZ, C3);
    transpose_kh<<<dim3(C_SZ / 32, C_SZ / 32), dim3(32, 8)>>>(W_proj, wtp, C_SZ, C_SZ);

    // 1) qkv = x @ W_attn + b_attn
    hgemm_bias<<<dim3(C3 / HBN_T, M_ROWS / HBM_T), 256, HGEMM_SMEM>>>(
        xh, wta, b_attn, qkv, M_ROWS, C3, C_SZ);

    // 2) pooled K/V
    pool0<<<dim3(8, BH), 256>>>(qkv, kp, vp);
    pool_rest<<<BH, 256>>>(kp, vp);

    // 3) fused MLA attention (tensor cores) -> fp16
    mla_attn<<<dim3(T_SZ / MW, BH), 256, ATTN2_BYTES>>>(qkv, kp, vp, ah);

    // 4) out = attn @ W_proj + b_proj
    hgemm_bias<<<dim3(C_SZ / HBN_T, M_ROWS / HBM_T), 256, HGEMM_SMEM>>>(
        ah, wtp, b_proj, out, M_ROWS, C_SZ, C_SZ);
}

// round 8
// speedup vs baseline: 5.6948x; 1.1024x over previous
#include <cuda_runtime.h>
#include <cuda_fp16.h>
#include <cstdint>

// ---------------------------------------------------------------------------
// Problem constants
// ---------------------------------------------------------------------------
#define B_SZ   8
#define T_SZ   2048
#define C_SZ   1024
#define H_SZ   16
#define DH     64
#define BH     (B_SZ * H_SZ)     // 128
#define C3     (3 * C_SZ)        // 3072
#define M_ROWS (B_SZ * T_SZ)     // 16384
#define MW     64
#define PP     8
#define NLEV   4

__device__ __constant__ size_t POOL_OFF[4] = {
    0,
    (size_t)BH * 256 * DH,
    (size_t)BH * 256 * DH + (size_t)BH * 128 * DH,
    (size_t)BH * 256 * DH + (size_t)BH * 128 * DH + (size_t)BH * 64 * DH
};
#define POOL_TOTAL ((size_t)BH * (256 + 128 + 64 + 32) * DH)

// ---------------------------------------------------------------------------
// Scratch (static device allocations)
// ---------------------------------------------------------------------------
__device__ __half g_qkv_h [(size_t)M_ROWS * C3];     // 100 MB fp16 qkv
__device__ __half g_x_h   [(size_t)M_ROWS * C_SZ];
__device__ __half g_attn_h[(size_t)M_ROWS * C_SZ];
__device__ __half g_kpool [POOL_TOTAL];
__device__ __half g_vpool [POOL_TOTAL];
__device__ __half g_wt_attn[(size_t)C3 * C_SZ];
__device__ __half g_wt_proj[(size_t)C_SZ * C_SZ];

// ===========================================================================
// PTX helpers
// ===========================================================================
__device__ __forceinline__ uint32_t smem_u32(const void* p) {
    uint32_t a;
    asm("{ .reg .u64 t; cvta.to.shared.u64 t, %1; cvt.u32.u64 %0, t; }" : "=r"(a) : "l"(p));
    return a;
}
__device__ __forceinline__ void cp_async16(uint32_t saddr, const void* g) {
    asm volatile("cp.async.cg.shared.global [%0], [%1], 16;" :: "r"(saddr), "l"(g));
}
__device__ __forceinline__ void cp_commit() {
    asm volatile("cp.async.commit_group;" ::: "memory");
}
template <int N>
__device__ __forceinline__ void cp_wait() {
    asm volatile("cp.async.wait_group %0;" :: "n"(N) : "memory");
}
__device__ __forceinline__ void ldm_x4(uint32_t& r0, uint32_t& r1, uint32_t& r2,
                                       uint32_t& r3, uint32_t addr) {
    asm volatile("ldmatrix.sync.aligned.m8n8.x4.shared.b16 {%0,%1,%2,%3}, [%4];"
                 : "=r"(r0), "=r"(r1), "=r"(r2), "=r"(r3) : "r"(addr));
}
__device__ __forceinline__ void ldm_x4t(uint32_t& r0, uint32_t& r1, uint32_t& r2,
                                        uint32_t& r3, uint32_t addr) {
    asm volatile("ldmatrix.sync.aligned.m8n8.x4.trans.shared.b16 {%0,%1,%2,%3}, [%4];"
                 : "=r"(r0), "=r"(r1), "=r"(r2), "=r"(r3) : "r"(addr));
}
__device__ __forceinline__ void mma16816(float* d, const uint32_t* a, const uint32_t* b) {
    asm volatile(
        "mma.sync.aligned.m16n8k16.row.col.f32.f16.f16.f32 "
        "{%0,%1,%2,%3}, {%4,%5,%6,%7}, {%8,%9}, {%0,%1,%2,%3};"
        : "+f"(d[0]), "+f"(d[1]), "+f"(d[2]), "+f"(d[3])
        : "r"(a[0]), "r"(a[1]), "r"(a[2]), "r"(a[3]), "r"(b[0]), "r"(b[1]));
}

// ===========================================================================
// Prep kernels
// ===========================================================================
__global__ void convert_f2h(const float* __restrict__ in, __half* __restrict__ out,
                            size_t n)
{
    const size_t i = ((size_t)blockIdx.x * blockDim.x + threadIdx.x) * 4;
    if (i < n) {
        float4 v = *(const float4*)(in + i);
        *(__half2*)(out + i)     = __floats2half2_rn(v.x, v.y);
        *(__half2*)(out + i + 2) = __floats2half2_rn(v.z, v.w);
    }
}

__global__ void transpose_kh(const float* __restrict__ W, __half* __restrict__ Wt,
                             int K, int N)
{
    __shared__ float t[32][33];
    const int x = blockIdx.x * 32 + threadIdx.x;
    const int y = blockIdx.y * 32 + threadIdx.y;
#pragma unroll
    for (int j = 0; j < 32; j += 8)
        t[threadIdx.y + j][threadIdx.x] = W[(size_t)(y + j) * N + x];
    __syncthreads();
    const int xo = blockIdx.y * 32 + threadIdx.x;
    const int yo = blockIdx.x * 32 + threadIdx.y;
#pragma unroll
    for (int j = 0; j < 32; j += 8)
        Wt[(size_t)(yo + j) * K + xo] = __float2half(t[threadIdx.x][threadIdx.y + j]);
}

// ===========================================================================
// HGEMM (128x128x32, warp 64x32), 5-stage cp.async. HALF_OUT selects C dtype.
// ===========================================================================
#define HBM_T 128
#define HBN_T 128
#define HBK_T 32
#define HSTAGES 5
#define HPITCH 80
#define HSTAGE_BYTES (2 * 128 * HPITCH)                 // 20480
#define HGEMM_SMEM (HSTAGES * HSTAGE_BYTES)             // 102400

template <int HALF_OUT>
__global__ __launch_bounds__(256)
void hgemm_bias(const __half* __restrict__ Ah, const __half* __restrict__ Bh,
                const float* __restrict__ bias, void* __restrict__ Cout,
                int M, int N, int K)
{
    extern __shared__ char smem[];
    const uint32_t sb = smem_u32(smem);
    const int tid  = threadIdx.x;
    const int wid  = tid >> 5;
    const int lane = tid & 31;

    const int row0 = blockIdx.y * HBM_T;
    const int col0 = blockIdx.x * HBN_T;
    const int m0   = (wid & 1) * 64;
    const int n0   = (wid >> 1) * 32;
    const int NT   = K / HBK_T;

    const int mat = lane >> 3, li = lane & 7;
    const int rowA = (mat & 1) * 8 + li;
    const int kA   = (mat >> 1) * 8;
    const int rowB = (mat >> 1) * 8 + li;
    const int kB   = (mat & 1) * 8;

    float acc[4][4][4];
#pragma unroll
    for (int i = 0; i < 4; i++)
#pragma unroll
        for (int j = 0; j < 4; j++)
#pragma unroll
            for (int r = 0; r < 4; r++) acc[i][j][r] = 0.f;

    auto load_tile = [&](int t) {
        const uint32_t sA = sb + (t % HSTAGES) * HSTAGE_BYTES;
        const uint32_t sB = sA + 128 * HPITCH;
        const int k0 = t * HBK_T;
#pragma unroll
        for (int i = 0; i < 2; i++) {
            const int id = i * 256 + tid;
            const int r = id >> 2, c = id & 3;
            cp_async16(sA + r * HPITCH + c * 16, Ah + (size_t)(row0 + r) * K + k0 + c * 8);
        }
#pragma unroll
        for (int i = 0; i < 2; i++) {
            const int id = i * 256 + tid;
            const int r = id >> 2, c = id & 3;
            cp_async16(sB + r * HPITCH + c * 16, Bh + (size_t)(col0 + r) * K + k0 + c * 8);
        }
    };

    for (int t = 0; t < HSTAGES - 1; t++) { load_tile(t); cp_commit(); }

    for (int kt = 0; kt < NT; kt++) {
        cp_wait<HSTAGES - 2>();
        __syncthreads();
        const int pf = kt + HSTAGES - 1;
        if (pf < NT) load_tile(pf);
        cp_commit();

        const uint32_t sA = sb + (kt % HSTAGES) * HSTAGE_BYTES;
        const uint32_t sB = sA + 128 * HPITCH;
#pragma unroll
        for (int kc = 0; kc < 2; kc++) {
            uint32_t af[4][4], bf[2][4];
#pragma unroll
            for (int mt = 0; mt < 4; mt++)
                ldm_x4(af[mt][0], af[mt][1], af[mt][2], af[mt][3],
                       sA + (m0 + mt * 16 + rowA) * HPITCH + (kc * 16 + kA) * 2);
#pragma unroll
            for (int np = 0; np < 2; np++)
                ldm_x4(bf[np][0], bf[np][1], bf[np][2], bf[np][3],
                       sB + (n0 + np * 16 + rowB) * HPITCH + (kc * 16 + kB) * 2);
#pragma unroll
            for (int mt = 0; mt < 4; mt++)
#pragma unroll
                for (int nt = 0; nt < 4; nt++)
                    mma16816(acc[mt][nt], af[mt], &bf[nt >> 1][(nt & 1) * 2]);
        }
    }
    cp_wait<0>();

#pragma unroll
    for (int mt = 0; mt < 4; mt++) {
#pragma unroll
        for (int nt = 0; nt < 4; nt++) {
            const int r  = row0 + m0 + mt * 16 + (lane >> 2);
            const int cc = col0 + n0 + nt * 8 + (lane & 3) * 2;
            const float b0 = bias[cc], b1 = bias[cc + 1];
            if (HALF_OUT) {
                __half* C = (__half*)Cout;
                *(__half2*)(C + (size_t)r * N + cc) =
                    __floats2half2_rn(acc[mt][nt][0] + b0, acc[mt][nt][1] + b1);
                *(__half2*)(C + (size_t)(r + 8) * N + cc) =
                    __floats2half2_rn(acc[mt][nt][2] + b0, acc[mt][nt][3] + b1);
            } else {
                float* C = (float*)Cout;
                float2 v0 = { acc[mt][nt][0] + b0, acc[mt][nt][1] + b1 };
                float2 v1 = { acc[mt][nt][2] + b0, acc[mt][nt][3] + b1 };
                *(float2*)(C + (size_t)r * N + cc)       = v0;
                *(float2*)(C + (size_t)(r + 8) * N + cc) = v1;
            }
        }
    }
}

// ---------------------------------------------------------------------------
// Pooling (fp16 in/out, fp32 accumulate), half2-vectorized
// ---------------------------------------------------------------------------
__global__ void pool0(const __half* __restrict__ qkv,
                      __half* __restrict__ kp, __half* __restrict__ vp)
{
    const int bh = blockIdx.y;
    const int b = bh >> 4, h = bh & 15;
    const size_t kb = (size_t)b * T_SZ * C3 + h * DH + C_SZ;
    const size_t vb = kb + C_SZ;

    for (int idx = threadIdx.x; idx < 32 * 32; idx += 256) {
        const int pi = blockIdx.x * 32 + (idx >> 5);
        const int d2 = (idx & 31) * 2;
        float skx = 0.f, sky = 0.f, svx = 0.f, svy = 0.f;
        const int t0 = pi * 8;
#pragma unroll
        for (int i = 0; i < 8; i++) {
            float2 k2 = __half22float2(*(const __half2*)(qkv + kb + (size_t)(t0 + i) * C3 + d2));
            float2 v2 = __half22float2(*(const __half2*)(qkv + vb + (size_t)(t0 + i) * C3 + d2));
            skx += k2.x; sky += k2.y; svx += v2.x; svy += v2.y;
        }
        const size_t o = ((size_t)bh * 256 + pi) * DH + d2;
        *(__half2*)(kp + o) = __floats2half2_rn(skx * 0.125f, sky * 0.125f);
        *(__half2*)(vp + o) = __floats2half2_rn(svx * 0.125f, svy * 0.125f);
    }
}

__global__ void pool_rest(__half* __restrict__ kp, __half* __restrict__ vp)
{
    const int bh = blockIdx.x;
    for (int l = 1; l <= 3; l++) {
        const int nl = 256 >> l;
        const size_t src = POOL_OFF[l - 1] + (size_t)bh * (nl * 2) * DH;
        const size_t dst = POOL_OFF[l]     + (size_t)bh * nl * DH;
        for (int idx = threadIdx.x; idx < nl * 32; idx += 256) {
            const int pi = idx >> 5, d2 = (idx & 31) * 2;
            {
                float2 a = __half22float2(*(const __half2*)(kp + src + (size_t)(2 * pi) * DH + d2));
                float2 c = __half22float2(*(const __half2*)(kp + src + (size_t)(2 * pi + 1) * DH + d2));
                *(__half2*)(kp + dst + (size_t)pi * DH + d2) =
                    __floats2half2_rn(0.5f * (a.x + c.x), 0.5f * (a.y + c.y));
            }
            {
                float2 a = __half22float2(*(const __half2*)(vp + src + (size_t)(2 * pi) * DH + d2));
                float2 c = __half22float2(*(const __half2*)(vp + src + (size_t)(2 * pi + 1) * DH + d2));
                *(__half2*)(vp + dst + (size_t)pi * DH + d2) =
                    __floats2half2_rn(0.5f * (a.x + c.x), 0.5f * (a.y + c.y));
            }
        }
        __syncthreads();
    }
}

// ---------------------------------------------------------------------------
// Fused MLA attention — tensor cores, fp16 qkv input (no conversion on loads).
// smem: sQh fp16 [64][72] @0 (9216) | sKh fp16 [160][72] @9216 (23040)
//       sS fp32 [64][164] @32256 (41984) | sWh fp16 [64][168] @74240 (21504)
// ---------------------------------------------------------------------------
#define AQH 0
#define AKH 9216
#define ASS 32256
#define AWH 74240
#define ATTN2_BYTES 95744
#define QP  72
#define KP  72
#define SP  164
#define WP  168

__global__ __launch_bounds__(256, 2)
void mla_attn(const __half* __restrict__ qkv,
              const __half* __restrict__ kpool,
              const __half* __restrict__ vpool,
              __half* __restrict__ o)
{
    extern __shared__ char smem[];
    const uint32_t sb = smem_u32(smem);
    float* sS = (float*)(smem + ASS);
    __half* sWh = (__half*)(smem + AWH);

    const int qb  = blockIdx.x;
    const int bh  = blockIdx.y;
    const int b   = bh >> 4, h = bh & 15;
    const int tid = threadIdx.x;
    const int wid = tid >> 5;
    const int lane = tid & 31;

    const size_t baseQ = (size_t)b * T_SZ * C3 + h * DH;
    const size_t baseK = baseQ + C_SZ;
    const size_t baseV = baseQ + 2 * C_SZ;

    const int mat = lane >> 3, li = lane & 7;
    const int rowA = (mat & 1) * 8 + li;
    const int kA   = (mat >> 1) * 8;
    const int rowB = (mat >> 1) * 8 + li;
    const int kB   = (mat & 1) * 8;

    const __half2 s2 = __half2half2(__float2half(0.125f));

    // --- load Q (x 1/8, exact in fp16) ---
    for (int i = tid; i < 64 * 8; i += 256) {
        const int r = i >> 3, c = (i & 7) * 8;
        uint4 v = *(const uint4*)(qkv + baseQ + (size_t)(qb * MW + r) * C3 + c);
        __half2* hv = (__half2*)&v;
#pragma unroll
        for (int k = 0; k < 4; k++) hv[k] = __hmul2(hv[k], s2);
        *(uint4*)(smem + AQH + r * (QP * 2) + c * 2) = v;
    }
    // --- load K (fine 128 + coarse 32) ---
    for (int i = tid; i < 160 * 8; i += 256) {
        const int r = i >> 3, c = (i & 7) * 8;
        uint4 v = {0u, 0u, 0u, 0u};
        if (r < 128) {
            const int t = qb * MW - MW + r;
            if (t >= 0) v = *(const uint4*)(qkv + baseK + (size_t)t * C3 + c);
        } else {
            const int rr = r - 128, l0 = rr >> 3, ix = rr & 7;
            const int cb = (qb >> l0) - 1;
            if (cb >= 0) {
                const int nl = 256 >> l0;
                v = *(const uint4*)(kpool + POOL_OFF[l0] +
                                    ((size_t)bh * nl + cb * PP + ix) * DH + c);
            }
        }
        *(uint4*)(smem + AKH + r * (KP * 2) + c * 2) = v;
    }
    __syncthreads();

    // --- scores: warp tile 16q x 80t, k=64 ---
    {
        const int q16   = (wid & 3) * 16;
        const int thalf = (wid >> 2) * 80;
        float acc[10][4];
#pragma unroll
        for (int f = 0; f < 10; f++)
#pragma unroll
            for (int r = 0; r < 4; r++) acc[f][r] = 0.f;
#pragma unroll
        for (int ks = 0; ks < 4; ks++) {
            const int k0 = ks * 16;
            uint32_t a[4];
            ldm_x4(a[0], a[1], a[2], a[3],
                   sb + AQH + (q16 + rowA) * (QP * 2) + (k0 + kA) * 2);
            uint32_t bk[5][4];
#pragma unroll
            for (int np = 0; np < 5; np++)
                ldm_x4(bk[np][0], bk[np][1], bk[np][2], bk[np][3],
                       sb + AKH + (thalf + np * 16 + rowB) * (KP * 2) + (k0 + kB) * 2);
#pragma unroll
            for (int f = 0; f < 10; f++)
                mma16816(acc[f], a, &bk[f >> 1][(f & 1) * 2]);
        }
#pragma unroll
        for (int f = 0; f < 10; f++) {
            const int n = thalf + f * 8 + (lane & 3) * 2;
            const int r = q16 + (lane >> 2);
            *(float2*)&sS[r * SP + n]       = { acc[f][0], acc[f][1] };
            *(float2*)&sS[(r + 8) * SP + n] = { acc[f][2], acc[f][3] };
        }
    }
    __syncthreads();

    // --- overwrite sKh with V ---
    for (int i = tid; i < 160 * 8; i += 256) {
        const int r = i >> 3, c = (i & 7) * 8;
        uint4 v = {0u, 0u, 0u, 0u};
        if (r < 128) {
            const int t = qb * MW - MW + r;
            if (t >= 0) v = *(const uint4*)(qkv + baseV + (size_t)t * C3 + c);
        } else {
            const int rr = r - 128, l0 = rr >> 3, ix = rr & 7;
            const int cb = (qb >> l0) - 1;
            if (cb >= 0) {
                const int nl = 256 >> l0;
                v = *(const uint4*)(vpool + POOL_OFF[l0] +
                                    ((size_t)bh * nl + cb * PP + ix) * DH + c);
            }
        }
        *(uint4*)(smem + AKH + r * (KP * 2) + c * 2) = v;
    }

    // --- cross-level softmax (fp32) -> fp16 weights ---
    {
        const int qi = tid >> 2, sub = tid & 3;
        float* row = sS + qi * SP;
        __half* wrow = sWh + qi * WP;
        const int lo = qi + 1, hi = qi + 64;
        const int j0 = sub * 32;

        float mx = -1e30f;
#pragma unroll
        for (int j = 0; j < 32; j++) {
            const int t = j0 + j;
            if (t >= lo && t <= hi) mx = fmaxf(mx, row[t]);
        }
        mx = fmaxf(mx, __shfl_xor_sync(0xffffffffu, mx, 1));
        mx = fmaxf(mx, __shfl_xor_sync(0xffffffffu, mx, 2));

        float mc = -1e30f;
#pragma unroll
        for (int i = 0; i < 8; i++) mc = fmaxf(mc, row[128 + sub * 8 + i]);
        float mcm = fminf(mc, __shfl_xor_sync(0xffffffffu, mc, 1));
        mcm = fminf(mcm, __shfl_xor_sync(0xffffffffu, mcm, 2));
        const float mn = fminf(mx, mcm);

        float es = 0.f;
        float ef[32], ec[8];
#pragma unroll
        for (int j = 0; j < 32; j++) {
            const int t = j0 + j;
            float e = 0.f;
            if (t >= lo && t <= hi) { e = __expf(row[t] - mn); es += e; }
            ef[j] = e;
        }
        const float scl = (float)(8 << sub);
#pragma unroll
        for (int i = 0; i < 8; i++) {
            const float e = __expf(row[128 + sub * 8 + i] - mn) * scl;
            ec[i] = e;
            es += e;
        }
        es += __shfl_xor_sync(0xffffffffu, es, 1);
        es += __shfl_xor_sync(0xffffffffu, es, 2);
        const float inv = 1.f / es;
#pragma unroll
        for (int j = 0; j < 32; j++) wrow[j0 + j] = __float2half(ef[j] * inv);
#pragma unroll
        for (int i = 0; i < 8; i++) wrow[128 + sub * 8 + i] = __float2half(ec[i] * inv);
    }
    __syncthreads();

    // --- stage 2: O(64x64) = W(64x160) @ V(160x64) ---
    {
        const int q16 = (wid & 3) * 16;
        const int d0  = (wid >> 2) * 32;
        float acc[4][4];
#pragma unroll
        for (int f = 0; f < 4; f++)
#pragma unroll
            for (int r = 0; r < 4; r++) acc[f][r] = 0.f;
#pragma unroll
        for (int ks = 0; ks < 10; ks++) {
            const int t0 = ks * 16;
            uint32_t a[4];
            ldm_x4(a[0], a[1], a[2], a[3],
                   sb + AWH + (q16 + rowA) * (WP * 2) + (t0 + kA) * 2);
            uint32_t bv[2][4];
#pragma unroll
            for (int g = 0; g < 2; g++)
                ldm_x4t(bv[g][0], bv[g][1], bv[g][2], bv[g][3],
                        sb + AKH + (t0 + (lane & 15)) * (KP * 2)
                           + (d0 + g * 16 + ((lane >> 4) << 3)) * 2);
#pragma unroll
            for (int f = 0; f < 4; f++)
                mma16816(acc[f], a, &bv[f >> 1][(f & 1) * 2]);
        }
#pragma unroll
        for (int f = 0; f < 4; f++) {
            const int col = d0 + f * 8 + (lane & 3) * 2;
            const int r0  = q16 + (lane >> 2);
            const int tq0 = qb * MW + r0;
            __half2 v0 = __floats2half2_rn(acc[f][0], acc[f][1]);
            __half2 v1 = __floats2half2_rn(acc[f][2], acc[f][3]);
            *(__half2*)(o + ((size_t)b * T_SZ + tq0) * C_SZ + h * DH + col)     = v0;
            *(__half2*)(o + ((size_t)b * T_SZ + tq0 + 8) * C_SZ + h * DH + col) = v1;
        }
    }
}

// ---------------------------------------------------------------------------
// Launch
// ---------------------------------------------------------------------------
extern "C" void kernel_launch(void* const* d_in, const int* in_sizes, int n_in,
                              void* d_out, int out_size)
{
    (void)in_sizes; (void)n_in; (void)out_size;
    const float* x      = (const float*)d_in[0];
    const float* W_attn = (const float*)d_in[1];
    const float* b_attn = (const float*)d_in[2];
    const float* W_proj = (const float*)d_in[3];
    const float* b_proj = (const float*)d_in[4];
    float* out = (float*)d_out;

    __half *qkvh, *xh, *ah, *kp, *vp, *wta, *wtp;
    cudaGetSymbolAddress((void**)&qkvh, g_qkv_h);
    cudaGetSymbolAddress((void**)&xh,   g_x_h);
    cudaGetSymbolAddress((void**)&ah,   g_attn_h);
    cudaGetSymbolAddress((void**)&kp,   g_kpool);
    cudaGetSymbolAddress((void**)&vp,   g_vpool);
    cudaGetSymbolAddress((void**)&wta,  g_wt_attn);
    cudaGetSymbolAddress((void**)&wtp,  g_wt_proj);

    cudaFuncSetAttribute(mla_attn, cudaFuncAttributeMaxDynamicSharedMemorySize,
                         ATTN2_BYTES);
    cudaFuncSetAttribute(hgemm_bias<0>, cudaFuncAttributeMaxDynamicSharedMemorySize,
                         HGEMM_SMEM);
    cudaFuncSetAttribute(hgemm_bias<1>, cudaFuncAttributeMaxDynamicSharedMemorySize,
                         HGEMM_SMEM);

    // 0) prep
    const size_t nx = (size_t)M_ROWS * C_SZ;
    convert_f2h<<<(unsigned)((nx / 4 + 255) / 256), 256>>>(x, xh, nx);
    transpose_kh<<<dim3(C3 / 32, C_SZ / 32), dim3(32, 8)>>>(W_attn, wta, C_SZ, C3);
    transpose_kh<<<dim3(C_SZ / 32, C_SZ / 32), dim3(32, 8)>>>(W_proj, wtp, C_SZ, C_SZ);

    // 1) qkv = x @ W_attn + b_attn  (fp16 out)
    hgemm_bias<1><<<dim3(C3 / HBN_T, M_ROWS / HBM_T), 256, HGEMM_SMEM>>>(
        xh, wta, b_attn, qkvh, M_ROWS, C3, C_SZ);

    // 2) pooled K/V (fp16)
    pool0<<<dim3(8, BH), 256>>>(qkvh, kp, vp);
    pool_rest<<<BH, 256>>>(kp, vp);

    // 3) fused MLA attention (tensor cores) -> fp16
    mla_attn<<<dim3(T_SZ / MW, BH), 256, ATTN2_BYTES>>>(qkvh, kp, vp, ah);

    // 4) out = attn @ W_proj + b_proj  (fp32 out)
    hgemm_bias<0><<<dim3(C_SZ / HBN_T, M_ROWS / HBM_T), 256, HGEMM_SMEM>>>(
        ah, wtp, b_proj, out, M_ROWS, C_SZ, C_SZ);
}